// round 14
// baseline (speedup 1.0000x reference)
#include <cuda_runtime.h>
#include <cuda_bf16.h>
#include <cstdint>

// ---------------------------------------------------------------------------
// MHA without softmax, folded:
//   out[b] = q[b] @ G_b + c_b,  G_b = W_q · blockdiag(M_b) · W_o,
//   M_b = K_b^T V_b / sqrt(dk)
// GEMMs (bf16 [hi|lo] K=1536, 3-segment): merged KV (8192 rows), G (1536),
// final (4096). R14: t_kernel emits Text directly + carries cvec; NCHUNK=16;
// vectorized mask scan.
// ---------------------------------------------------------------------------

#define D_MODEL 768
#define SEQ     2048
#define BATCH   2
#define NTOK    (BATCH*SEQ)          // 4096
#define NHEAD   12
#define DK      64
#define BHTOT   (BATCH*NHEAD)        // 24
#define NCHUNK  16
#define CHUNK_T (SEQ/NCHUNK)         // 128
#define SCALE   0.125f
#define NEGV    (-1000000000.0f)

#define GK2     1536                 // split K: [hi | lo]
#define BK      32
#define SEGSTEP (D_MODEL/BK)         // 24
#define NKSTEP  (3*SEGSTEP)          // 72
#define SM_ABYTES  8192              // 128 rows * 64B
#define SM_B64     4096              // 64 rows * 64B
#define STB64  (SM_ABYTES + SM_B64)
#define W64_STAGES 4
#define G64_STAGES 3

// Scratch (allocation-free)
__device__ float g_KVp[2*NTOK*D_MODEL];       // rows 0..4095 = Kp, 4096.. = Vp
__device__ float g_Mpart[BHTOT*NCHUNK*DK*DK];
__device__ float g_M[BHTOT*DK*DK];
__device__ float g_G[2*D_MODEL*D_MODEL];
__device__ float g_cvec[2*D_MODEL];
__device__ float g_zero[D_MODEL];
__device__ float g_biasKV[2*D_MODEL];
__device__ __nv_bfloat16 g_Qext[(size_t)NTOK*GK2];
__device__ __nv_bfloat16 g_Aext[(size_t)2*NTOK*GK2];
__device__ __nv_bfloat16 g_Text[(size_t)2*D_MODEL*GK2];
__device__ __nv_bfloat16 g_Wext[(size_t)2*D_MODEL*GK2];
__device__ __nv_bfloat16 g_Woext[(size_t)D_MODEL*GK2];
__device__ __nv_bfloat16 g_Gext[(size_t)2*D_MODEL*GK2];

// ---------------------------------------------------------------------------
// PTX helpers (generic sm_80+ ISA only)
// ---------------------------------------------------------------------------
__device__ __forceinline__ uint32_t smem_u32(const void* p) {
    uint32_t a;
    asm("{ .reg .u64 t; cvta.to.shared.u64 t, %1; cvt.u32.u64 %0, t; }" : "=r"(a) : "l"(p));
    return a;
}
__device__ __forceinline__ void cp16(uint32_t saddr, const void* g) {
    asm volatile("cp.async.cg.shared.global [%0], [%1], 16;" :: "r"(saddr), "l"(g));
}
#define CP_COMMIT() asm volatile("cp.async.commit_group;" ::: "memory")
#define CP_WAIT0()  asm volatile("cp.async.wait_group 0;" ::: "memory")
#define CP_WAIT1()  asm volatile("cp.async.wait_group 1;" ::: "memory")
#define CP_WAIT2()  asm volatile("cp.async.wait_group 2;" ::: "memory")

__device__ __forceinline__ void ldsm4(uint32_t* r, uint32_t addr) {
    asm volatile("ldmatrix.sync.aligned.m8n8.x4.shared.b16 {%0,%1,%2,%3}, [%4];"
                 : "=r"(r[0]), "=r"(r[1]), "=r"(r[2]), "=r"(r[3]) : "r"(addr));
}
__device__ __forceinline__ void mma16816(float* c, const uint32_t* a,
                                         uint32_t b0, uint32_t b1) {
    asm volatile(
        "mma.sync.aligned.m16n8k16.row.col.f32.bf16.bf16.f32 "
        "{%0,%1,%2,%3}, {%4,%5,%6,%7}, {%8,%9}, {%0,%1,%2,%3};"
        : "+f"(c[0]), "+f"(c[1]), "+f"(c[2]), "+f"(c[3])
        : "r"(a[0]), "r"(a[1]), "r"(a[2]), "r"(a[3]), "r"(b0), "r"(b1));
}
__device__ __forceinline__ uint32_t swz(int r, int c) {
    return (uint32_t)(r * 64 + ((c ^ ((r >> 1) & 3)) << 4));
}

#define KOFF_A(ks) (((ks) >= 2*SEGSTEP ? 768 : 0) + ((ks) % SEGSTEP) * BK)
#define KOFF_B(ks) ((((ks) >= SEGSTEP && (ks) < 2*SEGSTEP) ? 768 : 0) + ((ks) % SEGSTEP) * BK)

// ---------------------------------------------------------------------------
// Conversion bodies
// ---------------------------------------------------------------------------
__device__ __forceinline__ void act4_body(
    const float* __restrict__ in, __nv_bfloat16* __restrict__ out, int blk)
{
    const int idx = blk * 256 + threadIdx.x;
    const int e = idx * 4;
    const int r = e / D_MODEL, c = e - r * D_MODEL;
    float4 a = *(const float4*)(in + e);
    __nv_bfloat16 h0 = __float2bfloat16_rn(a.x), h1 = __float2bfloat16_rn(a.y);
    __nv_bfloat16 h2 = __float2bfloat16_rn(a.z), h3 = __float2bfloat16_rn(a.w);
    __nv_bfloat16 l0 = __float2bfloat16_rn(a.x - __bfloat162float(h0));
    __nv_bfloat16 l1 = __float2bfloat16_rn(a.y - __bfloat162float(h1));
    __nv_bfloat16 l2 = __float2bfloat16_rn(a.z - __bfloat162float(h2));
    __nv_bfloat16 l3 = __float2bfloat16_rn(a.w - __bfloat162float(h3));
    uint2 hv, lv;
    hv.x = (uint32_t)__bfloat16_as_ushort(h0) | ((uint32_t)__bfloat16_as_ushort(h1) << 16);
    hv.y = (uint32_t)__bfloat16_as_ushort(h2) | ((uint32_t)__bfloat16_as_ushort(h3) << 16);
    lv.x = (uint32_t)__bfloat16_as_ushort(l0) | ((uint32_t)__bfloat16_as_ushort(l1) << 16);
    lv.y = (uint32_t)__bfloat16_as_ushort(l2) | ((uint32_t)__bfloat16_as_ushort(l3) << 16);
    size_t ro = (size_t)r * GK2;
    *(uint2*)(out + ro + c)       = hv;
    *(uint2*)(out + ro + 768 + c) = lv;
}

__device__ __forceinline__ void wconv_body(
    const float* __restrict__ W, __nv_bfloat16* __restrict__ out,
    int k0, int n0, float (*t)[33])
{
    const int tx = threadIdx.x & 31, ty = threadIdx.x >> 5;
    #pragma unroll
    for (int i = 0; i < 32; i += 8)
        t[ty + i][tx] = W[(size_t)(k0 + ty + i) * D_MODEL + n0 + tx];
    __syncthreads();
    #pragma unroll
    for (int i = 0; i < 32; i += 8) {
        const int n = n0 + ty + i, k = k0 + tx;
        const float w = t[tx][ty + i];
        __nv_bfloat16 hi = __float2bfloat16_rn(w);
        __nv_bfloat16 lo = __float2bfloat16_rn(w - __bfloat162float(hi));
        size_t ro = (size_t)n * GK2;
        out[ro + k]       = hi;
        out[ro + 768 + k] = lo;
    }
}

// All six independent conversions in ONE launch.
#define ACTB 3072
__global__ __launch_bounds__(256) void convert_all(
    const float* __restrict__ k, const float* __restrict__ v,
    const float* __restrict__ q,
    const float* __restrict__ w_k, const float* __restrict__ w_v,
    const float* __restrict__ w_o)
{
    __shared__ float t[32][33];
    const int bx = blockIdx.x;
    if (bx < 3 * ACTB) {
        const int tsel = bx / ACTB, blk = bx - tsel * ACTB;
        const float* in = tsel == 0 ? k : (tsel == 1 ? v : q);
        __nv_bfloat16* out = tsel == 0 ? g_Aext
                           : (tsel == 1 ? g_Aext + (size_t)NTOK * GK2 : g_Qext);
        act4_body(in, out, blk);
    } else {
        const int wi = bx - 3 * ACTB;
        const int widx = wi / 576, b = wi - widx * 576;
        const float* W = widx == 0 ? w_k : (widx == 1 ? w_v : w_o);
        __nv_bfloat16* out = widx == 0 ? g_Wext
                           : (widx == 1 ? g_Wext + (size_t)D_MODEL * GK2 : g_Woext);
        wconv_body(W, out, (b % 24) * 32, (b / 24) * 32, t);
    }
}

// ---------------------------------------------------------------------------
// Big-GEMM: 128x64 CTA, 128 threads (4 warps 2x2), 64x32 warp tiles, 4 stages.
// ---------------------------------------------------------------------------
__global__ __launch_bounds__(128) void gemm_w64(
    const __nv_bfloat16* __restrict__ A,
    const __nv_bfloat16* __restrict__ B, size_t bStride,
    const float* __restrict__ bias, int biasStride,
    float* __restrict__ C, int segShift)
{
    __shared__ __align__(1024) char smem[W64_STAGES * STB64];
    const int tid  = threadIdx.x;
    const int lane = tid & 31, wid = tid >> 5;
    const int wm = wid & 1, wn = wid >> 1;          // 2 x 2 warps
    const int rowBase = blockIdx.y * 128;
    const int colBase = blockIdx.x * 64;
    const int seg = rowBase >> segShift;
    const uint32_t sbase = smem_u32(smem);

    const __nv_bfloat16* Ag = A + (size_t)rowBase * GK2;
    const __nv_bfloat16* Bg = B + (size_t)seg * bStride + (size_t)colBase * GK2;
    const float* bp = bias + (size_t)seg * biasStride;

    const int lr = tid >> 2;      // 0..31
    const int ac = tid & 3;

    float acc[4][4][4];
    #pragma unroll
    for (int mi = 0; mi < 4; mi++)
        #pragma unroll
        for (int j = 0; j < 4; j++)
            #pragma unroll
            for (int e = 0; e < 4; e++) acc[mi][j][e] = 0.0f;

    #pragma unroll
    for (int s = 0; s < W64_STAGES - 1; s++) {
        const int ka = KOFF_A(s), kb = KOFF_B(s);
        const uint32_t sa = sbase + s * STB64;
        const uint32_t sb = sa + SM_ABYTES;
        #pragma unroll
        for (int p = 0; p < 4; p++)
            cp16(sa + swz(lr + p * 32, ac), Ag + (size_t)(lr + p * 32) * GK2 + ka + ac * 8);
        #pragma unroll
        for (int p = 0; p < 2; p++)
            cp16(sb + swz(lr + p * 32, ac), Bg + (size_t)(lr + p * 32) * GK2 + kb + ac * 8);
        CP_COMMIT();
    }

    const int flr = lane & 15;
    const int flc = lane >> 4;

    for (int ks = 0; ks < NKSTEP; ks++) {
        const int rem = NKSTEP - 1 - ks;
        if (rem >= 2) { CP_WAIT2(); } else if (rem == 1) { CP_WAIT1(); } else { CP_WAIT0(); }
        __syncthreads();

        if (ks + W64_STAGES - 1 < NKSTEP) {
            const int kn = ks + W64_STAGES - 1;
            const int s  = kn % W64_STAGES;
            const int ka = KOFF_A(kn), kb = KOFF_B(kn);
            const uint32_t sa = sbase + s * STB64;
            const uint32_t sb = sa + SM_ABYTES;
            #pragma unroll
            for (int p = 0; p < 4; p++)
                cp16(sa + swz(lr + p * 32, ac), Ag + (size_t)(lr + p * 32) * GK2 + ka + ac * 8);
            #pragma unroll
            for (int p = 0; p < 2; p++)
                cp16(sb + swz(lr + p * 32, ac), Bg + (size_t)(lr + p * 32) * GK2 + kb + ac * 8);
            CP_COMMIT();
        }

        const uint32_t sa = sbase + (ks % W64_STAGES) * STB64;
        const uint32_t sb = sa + SM_ABYTES;
        #pragma unroll
        for (int kh = 0; kh < 2; kh++) {
            uint32_t afr[4][4], bfr[2][4];
            const int cc = kh * 2 + flc;
            #pragma unroll
            for (int mi = 0; mi < 4; mi++)
                ldsm4(afr[mi], sa + swz(wm * 64 + mi * 16 + flr, cc));
            #pragma unroll
            for (int ni = 0; ni < 2; ni++)
                ldsm4(bfr[ni], sb + swz(wn * 32 + ni * 16 + flr, cc));
            #pragma unroll
            for (int mi = 0; mi < 4; mi++)
                #pragma unroll
                for (int ni = 0; ni < 2; ni++)
                    #pragma unroll
                    for (int nn = 0; nn < 2; nn++)
                        mma16816(acc[mi][ni * 2 + nn], afr[mi],
                                 bfr[ni][nn], bfr[ni][nn + 2]);
        }
    }

    #pragma unroll
    for (int mi = 0; mi < 4; mi++) {
        const int row0 = rowBase + wm * 64 + mi * 16 + (lane >> 2);
        #pragma unroll
        for (int j = 0; j < 4; j++) {
            const int col = colBase + wn * 32 + j * 8 + (lane & 3) * 2;
            const float2 bv = *(const float2*)(bp + col);
            float2 o0, o1;
            o0.x = acc[mi][j][0] + bv.x; o0.y = acc[mi][j][1] + bv.y;
            o1.x = acc[mi][j][2] + bv.x; o1.y = acc[mi][j][3] + bv.y;
            *(float2*)(C + (size_t)row0 * D_MODEL + col) = o0;
            *(float2*)(C + (size_t)(row0 + 8) * D_MODEL + col) = o1;
        }
    }
}

// ---------------------------------------------------------------------------
// 128x64 HMMA GEMM @ 256 threads, occ 2, 3 stages (for the small G GEMM).
// ---------------------------------------------------------------------------
__global__ __launch_bounds__(256, 2) void gemm_hmma64(
    const __nv_bfloat16* __restrict__ A,
    const __nv_bfloat16* __restrict__ B, size_t bStride,
    const float* __restrict__ bias, int biasStride,
    float* __restrict__ C, int segShift)
{
    __shared__ __align__(1024) char smem[G64_STAGES * STB64];
    const int tid  = threadIdx.x;
    const int lane = tid & 31, wid = tid >> 5;
    const int wm = wid & 3, wn = wid >> 2;       // 4 x 2 warps
    const int rowBase = blockIdx.y * 128;
    const int colBase = blockIdx.x * 64;
    const int seg = rowBase >> segShift;
    const uint32_t sbase = smem_u32(smem);

    const __nv_bfloat16* Ag = A + (size_t)rowBase * GK2;
    const __nv_bfloat16* Bg = B + (size_t)seg * bStride + (size_t)colBase * GK2;
    const float* bp = bias + (size_t)seg * biasStride;

    const int lr = tid >> 2;
    const int ac = tid & 3;

    float acc[2][4][4];
    #pragma unroll
    for (int mi = 0; mi < 2; mi++)
        #pragma unroll
        for (int j = 0; j < 4; j++)
            #pragma unroll
            for (int e = 0; e < 4; e++) acc[mi][j][e] = 0.0f;

    #pragma unroll
    for (int s = 0; s < G64_STAGES - 1; s++) {
        const int ka = KOFF_A(s), kb = KOFF_B(s);
        const uint32_t sa = sbase + s * STB64;
        const uint32_t sb = sa + SM_ABYTES;
        cp16(sa + swz(lr, ac),      Ag + (size_t)lr * GK2 + ka + ac * 8);
        cp16(sa + swz(lr + 64, ac), Ag + (size_t)(lr + 64) * GK2 + ka + ac * 8);
        cp16(sb + swz(lr, ac),      Bg + (size_t)lr * GK2 + kb + ac * 8);
        CP_COMMIT();
    }

    const int flr = lane & 15;
    const int flc = lane >> 4;

    for (int ks = 0; ks < NKSTEP; ks++) {
        const int rem = NKSTEP - 1 - ks;
        if (rem >= 1) { CP_WAIT1(); } else { CP_WAIT0(); }
        __syncthreads();

        if (ks + G64_STAGES - 1 < NKSTEP) {
            const int kn = ks + G64_STAGES - 1;
            const int s  = kn % G64_STAGES;
            const int ka = KOFF_A(kn), kb = KOFF_B(kn);
            const uint32_t sa = sbase + s * STB64;
            const uint32_t sb = sa + SM_ABYTES;
            cp16(sa + swz(lr, ac),      Ag + (size_t)lr * GK2 + ka + ac * 8);
            cp16(sa + swz(lr + 64, ac), Ag + (size_t)(lr + 64) * GK2 + ka + ac * 8);
            cp16(sb + swz(lr, ac),      Bg + (size_t)lr * GK2 + kb + ac * 8);
            CP_COMMIT();
        }

        const uint32_t sa = sbase + (ks % G64_STAGES) * STB64;
        const uint32_t sb = sa + SM_ABYTES;
        #pragma unroll
        for (int kh = 0; kh < 2; kh++) {
            uint32_t afr[2][4], bfr[2][4];
            const int cc = kh * 2 + flc;
            #pragma unroll
            for (int mi = 0; mi < 2; mi++)
                ldsm4(afr[mi], sa + swz(wm * 32 + mi * 16 + flr, cc));
            #pragma unroll
            for (int ni = 0; ni < 2; ni++)
                ldsm4(bfr[ni], sb + swz(wn * 32 + ni * 16 + flr, cc));
            #pragma unroll
            for (int mi = 0; mi < 2; mi++)
                #pragma unroll
                for (int ni = 0; ni < 2; ni++)
                    #pragma unroll
                    for (int nn = 0; nn < 2; nn++)
                        mma16816(acc[mi][ni * 2 + nn], afr[mi],
                                 bfr[ni][nn], bfr[ni][nn + 2]);
        }
    }

    #pragma unroll
    for (int mi = 0; mi < 2; mi++) {
        const int row0 = rowBase + wm * 32 + mi * 16 + (lane >> 2);
        #pragma unroll
        for (int j = 0; j < 4; j++) {
            const int col = colBase + wn * 32 + j * 8 + (lane & 3) * 2;
            const float2 bv = *(const float2*)(bp + col);
            float2 o0, o1;
            o0.x = acc[mi][j][0] + bv.x; o0.y = acc[mi][j][1] + bv.y;
            o1.x = acc[mi][j][2] + bv.x; o1.y = acc[mi][j][3] + bv.y;
            *(float2*)(C + (size_t)row0 * D_MODEL + col) = o0;
            *(float2*)(C + (size_t)(row0 + 8) * D_MODEL + col) = o1;
        }
    }
}

// ---------------------------------------------------------------------------
// M = K^T V / sqrt(dk), per (b,h), chunked over t (NCHUNK=16, 128 rows/chunk).
// ---------------------------------------------------------------------------
__global__ __launch_bounds__(256) void kv_partial_kernel()
{
    const int chunk = blockIdx.x;
    const int bh    = blockIdx.y;
    const int b = bh / NHEAD, h = bh % NHEAD;
    const int tid = threadIdx.x;
    const int tx = tid & 15, ty = tid >> 4;

    __shared__ float ks[8][64];
    __shared__ float vs[8][64];

    const int rowBase = b * SEQ + chunk * CHUNK_T;
    const int colOff  = h * DK;

    const int li = tid * 2;
    const int lr = li >> 6;
    const int lc = li & 63;

    float acc[4][4];
    #pragma unroll
    for (int i = 0; i < 4; i++)
        #pragma unroll
        for (int j = 0; j < 4; j++) acc[i][j] = 0.0f;

    const float* Kp = g_KVp;
    const float* Vp = g_KVp + (size_t)NTOK * D_MODEL;

    for (int tt = 0; tt < CHUNK_T; tt += 8) {
        const size_t off = (size_t)(rowBase + tt + lr) * D_MODEL + colOff + lc;
        const float2 k2 = *(const float2*)(Kp + off);
        const float2 v2 = *(const float2*)(Vp + off);
        __syncthreads();
        ks[lr][lc] = k2.x; ks[lr][lc + 1] = k2.y;
        vs[lr][lc] = v2.x; vs[lr][lc + 1] = v2.y;
        __syncthreads();

        #pragma unroll
        for (int r = 0; r < 8; r++) {
            const float a0 = ks[r][ty * 4 + 0];
            const float a1 = ks[r][ty * 4 + 1];
            const float a2 = ks[r][ty * 4 + 2];
            const float a3 = ks[r][ty * 4 + 3];
            const float b0 = vs[r][tx * 4 + 0];
            const float b1 = vs[r][tx * 4 + 1];
            const float b2 = vs[r][tx * 4 + 2];
            const float b3 = vs[r][tx * 4 + 3];
            acc[0][0] += a0 * b0; acc[0][1] += a0 * b1; acc[0][2] += a0 * b2; acc[0][3] += a0 * b3;
            acc[1][0] += a1 * b0; acc[1][1] += a1 * b1; acc[1][2] += a1 * b2; acc[1][3] += a1 * b3;
            acc[2][0] += a2 * b0; acc[2][1] += a2 * b1; acc[2][2] += a2 * b2; acc[2][3] += a2 * b3;
            acc[3][0] += a3 * b0; acc[3][1] += a3 * b1; acc[3][2] += a3 * b2; acc[3][3] += a3 * b3;
        }
    }

    float* mp = g_Mpart + ((size_t)bh * NCHUNK + chunk) * DK * DK;
    #pragma unroll
    for (int i = 0; i < 4; i++)
        #pragma unroll
        for (int j = 0; j < 4; j++)
            mp[(ty * 4 + i) * DK + tx * 4 + j] = acc[i][j];
}

// Parallel reduce: grid (BHTOT, 16); each block reduces 256 elems over chunks.
__global__ __launch_bounds__(256) void kv_reduce_kernel()
{
    const int bh = blockIdx.x;
    const int e  = blockIdx.y * 256 + threadIdx.x;
    const float* base = g_Mpart + (size_t)bh * NCHUNK * DK * DK + e;
    float s = 0.0f;
    #pragma unroll
    for (int c = 0; c < NCHUNK; c++)
        s += base[(size_t)c * DK * DK];
    g_M[(size_t)bh * DK * DK + e] = s * SCALE;
}

// ---------------------------------------------------------------------------
// T_b[i][h*64+j] = sum_l W_q[i][h*64+l] * M_b[h][l][j], emitted directly as
// bf16 [hi|lo] into Text. blockIdx.y==12 rows carry the cvec computation.
// ---------------------------------------------------------------------------
__global__ __launch_bounds__(256) void t_kernel(
    const float* __restrict__ w_q, const float* __restrict__ b_q,
    const float* __restrict__ w_o, const float* __restrict__ b_o)
{
    const int tid = threadIdx.x;

    if (blockIdx.y == 12) {
        // cvec: 12 active blocks (2 batches x 6 m-tiles)
        if (blockIdx.x >= 12) return;
        __shared__ float bqM[D_MODEL];
        __shared__ float part[128];
        const int b  = blockIdx.x / 6;
        const int m0 = (blockIdx.x % 6) * 128;

        for (int n = tid; n < D_MODEL; n += 256) {
            const int h = n >> 6, j = n & 63;
            float s = 0.0f;
            #pragma unroll 16
            for (int i = 0; i < DK; i++)
                s += b_q[h * DK + i] * g_M[(size_t)(b * NHEAD + h) * DK * DK + i * DK + j];
            bqM[n] = s;
        }
        __syncthreads();

        const int m    = m0 + (tid & 127);
        const int half = tid >> 7;
        float s = 0.0f;
        for (int n = half * 384; n < half * 384 + 384; n++)
            s += bqM[n] * w_o[(size_t)n * D_MODEL + m];
        if (half) part[tid & 127] = s;
        __syncthreads();
        if (!half)
            g_cvec[b * D_MODEL + m] = s + part[tid & 127] + b_o[m];
        return;
    }

    const int bh = blockIdx.x;
    const int b = bh / NHEAD, h = bh % NHEAD;
    const int i0 = blockIdx.y * 64;

    __shared__ float Ms[DK][DK];
    __shared__ float Ws[DK][DK];

    for (int i = tid; i < DK * DK; i += 256) {
        Ms[i >> 6][i & 63] = g_M[(size_t)bh * DK * DK + i];
        Ws[i >> 6][i & 63] = w_q[(size_t)(i0 + (i >> 6)) * D_MODEL + h * DK + (i & 63)];
    }
    __syncthreads();

    const int c  = tid & 63;
    const int rg = tid >> 6;
    for (int r = rg * 16; r < rg * 16 + 16; r++) {
        float acc = 0.0f;
        #pragma unroll 16
        for (int l = 0; l < DK; l++) acc += Ws[r][l] * Ms[l][c];
        // emit bf16 hi/lo directly into Text
        __nv_bfloat16 hi = __float2bfloat16_rn(acc);
        __nv_bfloat16 lo = __float2bfloat16_rn(acc - __bfloat162float(hi));
        const size_t ro = (size_t)(b * D_MODEL + i0 + r) * GK2 + h * DK + c;
        g_Text[ro]       = hi;
        g_Text[ro + 768] = lo;
    }
}

// ---------------------------------------------------------------------------
// Finish: convert_w(G, both batches) -> Gext.
// ---------------------------------------------------------------------------
__global__ __launch_bounds__(256) void finish_kernel()
{
    __shared__ float t[32][33];
    const int bx = blockIdx.x;
    const int z = bx / 576, b = bx - z * 576;
    wconv_body(g_G + (size_t)z * D_MODEL * D_MODEL,
               g_Gext + (size_t)z * D_MODEL * GK2,
               (b % 24) * 32, (b / 24) * 32, t);
}

// ---------------------------------------------------------------------------
// Exact mask handling (projected through W_o). All-ones mask => pure scan.
// Vectorized int4 scan.
// ---------------------------------------------------------------------------
__global__ __launch_bounds__(256) void mask_correction_kernel(
    const int* __restrict__ mask, const float* __restrict__ q,
    const float* __restrict__ w_q, const float* __restrict__ b_q,
    const float* __restrict__ w_o, float* __restrict__ out)
{
    const int s = blockIdx.x;
    const int4* mrow = (const int4*)(mask + (size_t)s * SEQ);
    const float* Kp = g_KVp;
    const float* Vp = g_KVp + (size_t)NTOK * D_MODEL;
    for (int t4i = threadIdx.x; t4i < SEQ / 4; t4i += 256) {
        const int4 mq = mrow[t4i];
        if ((mq.x & mq.y & mq.z & mq.w) != 0) continue;
        #pragma unroll
        for (int u = 0; u < 4; u++) {
            const int mv = u == 0 ? mq.x : (u == 1 ? mq.y : (u == 2 ? mq.z : mq.w));
            if (mv != 0) continue;
            const int t = t4i * 4 + u;
            for (int b = 0; b < BATCH; b++) {
                const float* qrow = q + (size_t)(b * SEQ + s) * D_MODEL;
                const float* krow = Kp + (size_t)(b * SEQ + t) * D_MODEL;
                const float* vrow = Vp + (size_t)(b * SEQ + t) * D_MODEL;
                float* orow = out + (size_t)(b * SEQ + s) * D_MODEL;
                for (int h = 0; h < NHEAD; h++) {
                    float raw = 0.0f;
                    for (int l = 0; l < DK; l++) {
                        float qp = b_q[h * DK + l];
                        for (int i = 0; i < D_MODEL; i++)
                            qp += qrow[i] * w_q[(size_t)i * D_MODEL + h * DK + l];
                        raw += qp * krow[h * DK + l];
                    }
                    const float delta = NEGV - raw * SCALE;
                    for (int m = 0; m < D_MODEL; m++) {
                        float pv = 0.0f;
                        for (int j = 0; j < DK; j++)
                            pv += vrow[h * DK + j] * w_o[(size_t)(h * DK + j) * D_MODEL + m];
                        atomicAdd(&orow[m], delta * pv);
                    }
                }
            }
        }
    }
}

// ---------------------------------------------------------------------------
extern "C" void kernel_launch(void* const* d_in, const int* in_sizes, int n_in,
                              void* d_out, int out_size)
{
    const float* q    = (const float*)d_in[0];
    const float* k    = (const float*)d_in[1];
    const float* v    = (const float*)d_in[2];
    const int*   mask = (const int*)  d_in[3];
    const float* w_q  = (const float*)d_in[4];
    const float* b_q  = (const float*)d_in[5];
    const float* w_k  = (const float*)d_in[6];
    const float* b_k  = (const float*)d_in[7];
    const float* w_v  = (const float*)d_in[8];
    const float* b_v  = (const float*)d_in[9];
    const float* w_o  = (const float*)d_in[10];
    const float* b_o  = (const float*)d_in[11];
    float* out = (float*)d_out;

    float *KVp, *G, *cvec, *zero, *biasKV;
    __nv_bfloat16 *Qext, *Aext, *Text, *Wext, *Woext, *Gext;
    cudaGetSymbolAddress((void**)&KVp,    g_KVp);
    cudaGetSymbolAddress((void**)&G,      g_G);
    cudaGetSymbolAddress((void**)&cvec,   g_cvec);
    cudaGetSymbolAddress((void**)&zero,   g_zero);
    cudaGetSymbolAddress((void**)&biasKV, g_biasKV);
    cudaGetSymbolAddress((void**)&Qext,   g_Qext);
    cudaGetSymbolAddress((void**)&Aext,   g_Aext);
    cudaGetSymbolAddress((void**)&Text,   g_Text);
    cudaGetSymbolAddress((void**)&Wext,   g_Wext);
    cudaGetSymbolAddress((void**)&Woext,  g_Woext);
    cudaGetSymbolAddress((void**)&Gext,   g_Gext);

    const dim3 ggKV(D_MODEL / 64, 2 * NTOK / 128);         // (12, 64)
    const dim3 ggFin(D_MODEL / 64, NTOK / 128);            // (12, 32)
    const dim3 ggG(D_MODEL / 64, 2 * D_MODEL / 128);       // (12, 12)

    // 1. all independent conversions in one launch (k, v, q, wk, wv, wo)
    convert_all<<<3 * ACTB + 3 * 576, 256>>>(k, v, q, w_k, w_v, w_o);
    cudaMemcpyAsync(biasKV,           b_k, D_MODEL * sizeof(float), cudaMemcpyDeviceToDevice);
    cudaMemcpyAsync(biasKV + D_MODEL, b_v, D_MODEL * sizeof(float), cudaMemcpyDeviceToDevice);

    // 2. merged K+V projection
    gemm_w64<<<ggKV, 128>>>(Aext, Wext, (size_t)D_MODEL * GK2,
                            biasKV, D_MODEL, KVp, 12);

    // 3-4. M = K^T V / sqrt(dk)
    kv_partial_kernel<<<dim3(NCHUNK, BHTOT), 256>>>();
    kv_reduce_kernel<<<dim3(BHTOT, 16), 256>>>();

    // 5. T (direct bf16 emit) + cvec in one launch
    t_kernel<<<dim3(BHTOT, D_MODEL / 64 + 1), 256>>>(w_q, b_q, w_o, b_o);

    // 6. G_b = T_b @ W_o
    gemm_hmma64<<<ggG, 256>>>(Text, Woext, 0, zero, 0, G, 30);

    // 7. Gext conversion
    finish_kernel<<<1152, 256>>>();

    // 8. out[b] = q[b] @ G_b + cvec_b
    gemm_w64<<<ggFin, 128>>>(Qext, Gext, (size_t)D_MODEL * GK2,
                             cvec, D_MODEL, out, 11);

    // 9. exact mask handling (no-op for all-ones mask)
    mask_correction_kernel<<<SEQ, 256>>>(mask, q, w_q, b_q, w_o, out);
}

// round 15
// speedup vs baseline: 1.3143x; 1.3143x over previous
#include <cuda_runtime.h>
#include <cuda_bf16.h>
#include <cstdint>

// ---------------------------------------------------------------------------
// MHA without softmax, folded:
//   out[b] = q[b] @ G_b + c_b,  G_b = W_q · blockdiag(M_b) · W_o,
//   M_b = K_b^T V_b / sqrt(dk)
// GEMMs (bf16 [hi|lo] K=1536, 3-segment): merged KV (8192 rows), G (1536),
// final (4096). R15 = R13 config + int4 mask scan.
// ---------------------------------------------------------------------------

#define D_MODEL 768
#define SEQ     2048
#define BATCH   2
#define NTOK    (BATCH*SEQ)          // 4096
#define NHEAD   12
#define DK      64
#define BHTOT   (BATCH*NHEAD)        // 24
#define NCHUNK  32
#define CHUNK_T (SEQ/NCHUNK)         // 64
#define SCALE   0.125f
#define NEGV    (-1000000000.0f)

#define GK2     1536                 // split K: [hi | lo]
#define BK      32
#define SEGSTEP (D_MODEL/BK)         // 24
#define NKSTEP  (3*SEGSTEP)          // 72
#define SM_ABYTES  8192              // 128 rows * 64B
#define SM_B64     4096              // 64 rows * 64B
#define STB64  (SM_ABYTES + SM_B64)
#define W64_STAGES 4
#define G64_STAGES 3

// Scratch (allocation-free)
__device__ float g_KVp[2*NTOK*D_MODEL];       // rows 0..4095 = Kp, 4096.. = Vp
__device__ float g_Mpart[BHTOT*NCHUNK*DK*DK];
__device__ float g_M[BHTOT*DK*DK];
__device__ float g_T[2*D_MODEL*D_MODEL];
__device__ float g_G[2*D_MODEL*D_MODEL];
__device__ float g_cvec[2*D_MODEL];
__device__ float g_zero[D_MODEL];
__device__ float g_biasKV[2*D_MODEL];
__device__ __nv_bfloat16 g_Qext[(size_t)NTOK*GK2];
__device__ __nv_bfloat16 g_Aext[(size_t)2*NTOK*GK2];
__device__ __nv_bfloat16 g_Text[(size_t)2*D_MODEL*GK2];
__device__ __nv_bfloat16 g_Wext[(size_t)2*D_MODEL*GK2];
__device__ __nv_bfloat16 g_Woext[(size_t)D_MODEL*GK2];
__device__ __nv_bfloat16 g_Gext[(size_t)2*D_MODEL*GK2];

// ---------------------------------------------------------------------------
// PTX helpers (generic sm_80+ ISA only)
// ---------------------------------------------------------------------------
__device__ __forceinline__ uint32_t smem_u32(const void* p) {
    uint32_t a;
    asm("{ .reg .u64 t; cvta.to.shared.u64 t, %1; cvt.u32.u64 %0, t; }" : "=r"(a) : "l"(p));
    return a;
}
__device__ __forceinline__ void cp16(uint32_t saddr, const void* g) {
    asm volatile("cp.async.cg.shared.global [%0], [%1], 16;" :: "r"(saddr), "l"(g));
}
#define CP_COMMIT() asm volatile("cp.async.commit_group;" ::: "memory")
#define CP_WAIT0()  asm volatile("cp.async.wait_group 0;" ::: "memory")
#define CP_WAIT1()  asm volatile("cp.async.wait_group 1;" ::: "memory")
#define CP_WAIT2()  asm volatile("cp.async.wait_group 2;" ::: "memory")

__device__ __forceinline__ void ldsm4(uint32_t* r, uint32_t addr) {
    asm volatile("ldmatrix.sync.aligned.m8n8.x4.shared.b16 {%0,%1,%2,%3}, [%4];"
                 : "=r"(r[0]), "=r"(r[1]), "=r"(r[2]), "=r"(r[3]) : "r"(addr));
}
__device__ __forceinline__ void mma16816(float* c, const uint32_t* a,
                                         uint32_t b0, uint32_t b1) {
    asm volatile(
        "mma.sync.aligned.m16n8k16.row.col.f32.bf16.bf16.f32 "
        "{%0,%1,%2,%3}, {%4,%5,%6,%7}, {%8,%9}, {%0,%1,%2,%3};"
        : "+f"(c[0]), "+f"(c[1]), "+f"(c[2]), "+f"(c[3])
        : "r"(a[0]), "r"(a[1]), "r"(a[2]), "r"(a[3]), "r"(b0), "r"(b1));
}
__device__ __forceinline__ uint32_t swz(int r, int c) {
    return (uint32_t)(r * 64 + ((c ^ ((r >> 1) & 3)) << 4));
}

#define KOFF_A(ks) (((ks) >= 2*SEGSTEP ? 768 : 0) + ((ks) % SEGSTEP) * BK)
#define KOFF_B(ks) ((((ks) >= SEGSTEP && (ks) < 2*SEGSTEP) ? 768 : 0) + ((ks) % SEGSTEP) * BK)

// ---------------------------------------------------------------------------
// Conversion bodies (shared by mega-fused kernels)
// ---------------------------------------------------------------------------
__device__ __forceinline__ void act4_body(
    const float* __restrict__ in, __nv_bfloat16* __restrict__ out, int blk)
{
    const int idx = blk * 256 + threadIdx.x;
    const int e = idx * 4;
    const int r = e / D_MODEL, c = e - r * D_MODEL;
    float4 a = *(const float4*)(in + e);
    __nv_bfloat16 h0 = __float2bfloat16_rn(a.x), h1 = __float2bfloat16_rn(a.y);
    __nv_bfloat16 h2 = __float2bfloat16_rn(a.z), h3 = __float2bfloat16_rn(a.w);
    __nv_bfloat16 l0 = __float2bfloat16_rn(a.x - __bfloat162float(h0));
    __nv_bfloat16 l1 = __float2bfloat16_rn(a.y - __bfloat162float(h1));
    __nv_bfloat16 l2 = __float2bfloat16_rn(a.z - __bfloat162float(h2));
    __nv_bfloat16 l3 = __float2bfloat16_rn(a.w - __bfloat162float(h3));
    uint2 hv, lv;
    hv.x = (uint32_t)__bfloat16_as_ushort(h0) | ((uint32_t)__bfloat16_as_ushort(h1) << 16);
    hv.y = (uint32_t)__bfloat16_as_ushort(h2) | ((uint32_t)__bfloat16_as_ushort(h3) << 16);
    lv.x = (uint32_t)__bfloat16_as_ushort(l0) | ((uint32_t)__bfloat16_as_ushort(l1) << 16);
    lv.y = (uint32_t)__bfloat16_as_ushort(l2) | ((uint32_t)__bfloat16_as_ushort(l3) << 16);
    size_t ro = (size_t)r * GK2;
    *(uint2*)(out + ro + c)       = hv;
    *(uint2*)(out + ro + 768 + c) = lv;
}

__device__ __forceinline__ void wconv_body(
    const float* __restrict__ W, __nv_bfloat16* __restrict__ out,
    int k0, int n0, float (*t)[33])
{
    const int tx = threadIdx.x & 31, ty = threadIdx.x >> 5;
    #pragma unroll
    for (int i = 0; i < 32; i += 8)
        t[ty + i][tx] = W[(size_t)(k0 + ty + i) * D_MODEL + n0 + tx];
    __syncthreads();
    #pragma unroll
    for (int i = 0; i < 32; i += 8) {
        const int n = n0 + ty + i, k = k0 + tx;
        const float w = t[tx][ty + i];
        __nv_bfloat16 hi = __float2bfloat16_rn(w);
        __nv_bfloat16 lo = __float2bfloat16_rn(w - __bfloat162float(hi));
        size_t ro = (size_t)n * GK2;
        out[ro + k]       = hi;
        out[ro + 768 + k] = lo;
    }
}

// All six independent conversions in ONE launch.
#define ACTB 3072
__global__ __launch_bounds__(256) void convert_all(
    const float* __restrict__ k, const float* __restrict__ v,
    const float* __restrict__ q,
    const float* __restrict__ w_k, const float* __restrict__ w_v,
    const float* __restrict__ w_o)
{
    __shared__ float t[32][33];
    const int bx = blockIdx.x;
    if (bx < 3 * ACTB) {
        const int tsel = bx / ACTB, blk = bx - tsel * ACTB;
        const float* in = tsel == 0 ? k : (tsel == 1 ? v : q);
        __nv_bfloat16* out = tsel == 0 ? g_Aext
                           : (tsel == 1 ? g_Aext + (size_t)NTOK * GK2 : g_Qext);
        act4_body(in, out, blk);
    } else {
        const int wi = bx - 3 * ACTB;
        const int widx = wi / 576, b = wi - widx * 576;
        const float* W = widx == 0 ? w_k : (widx == 1 ? w_v : w_o);
        __nv_bfloat16* out = widx == 0 ? g_Wext
                           : (widx == 1 ? g_Wext + (size_t)D_MODEL * GK2 : g_Woext);
        wconv_body(W, out, (b % 24) * 32, (b / 24) * 32, t);
    }
}

// convert_act4 kept for the T matrix (mid-chain dependency)
__global__ __launch_bounds__(256) void convert_act4(
    const float* __restrict__ in, __nv_bfloat16* __restrict__ out, int total)
{
    int idx = blockIdx.x * 256 + threadIdx.x;
    if (idx * 4 >= total) return;
    act4_body(in, out, blockIdx.x);
}

// ---------------------------------------------------------------------------
// Big-GEMM: 128x64 CTA, 128 threads (4 warps 2x2), 64x32 warp tiles, 4 stages.
// ---------------------------------------------------------------------------
__global__ __launch_bounds__(128) void gemm_w64(
    const __nv_bfloat16* __restrict__ A,
    const __nv_bfloat16* __restrict__ B, size_t bStride,
    const float* __restrict__ bias, int biasStride,
    float* __restrict__ C, int segShift)
{
    __shared__ __align__(1024) char smem[W64_STAGES * STB64];
    const int tid  = threadIdx.x;
    const int lane = tid & 31, wid = tid >> 5;
    const int wm = wid & 1, wn = wid >> 1;          // 2 x 2 warps
    const int rowBase = blockIdx.y * 128;
    const int colBase = blockIdx.x * 64;
    const int seg = rowBase >> segShift;
    const uint32_t sbase = smem_u32(smem);

    const __nv_bfloat16* Ag = A + (size_t)rowBase * GK2;
    const __nv_bfloat16* Bg = B + (size_t)seg * bStride + (size_t)colBase * GK2;
    const float* bp = bias + (size_t)seg * biasStride;

    const int lr = tid >> 2;      // 0..31
    const int ac = tid & 3;

    float acc[4][4][4];
    #pragma unroll
    for (int mi = 0; mi < 4; mi++)
        #pragma unroll
        for (int j = 0; j < 4; j++)
            #pragma unroll
            for (int e = 0; e < 4; e++) acc[mi][j][e] = 0.0f;

    #pragma unroll
    for (int s = 0; s < W64_STAGES - 1; s++) {
        const int ka = KOFF_A(s), kb = KOFF_B(s);
        const uint32_t sa = sbase + s * STB64;
        const uint32_t sb = sa + SM_ABYTES;
        #pragma unroll
        for (int p = 0; p < 4; p++)
            cp16(sa + swz(lr + p * 32, ac), Ag + (size_t)(lr + p * 32) * GK2 + ka + ac * 8);
        #pragma unroll
        for (int p = 0; p < 2; p++)
            cp16(sb + swz(lr + p * 32, ac), Bg + (size_t)(lr + p * 32) * GK2 + kb + ac * 8);
        CP_COMMIT();
    }

    const int flr = lane & 15;
    const int flc = lane >> 4;

    for (int ks = 0; ks < NKSTEP; ks++) {
        const int rem = NKSTEP - 1 - ks;
        if (rem >= 2) { CP_WAIT2(); } else if (rem == 1) { CP_WAIT1(); } else { CP_WAIT0(); }
        __syncthreads();

        if (ks + W64_STAGES - 1 < NKSTEP) {
            const int kn = ks + W64_STAGES - 1;
            const int s  = kn % W64_STAGES;
            const int ka = KOFF_A(kn), kb = KOFF_B(kn);
            const uint32_t sa = sbase + s * STB64;
            const uint32_t sb = sa + SM_ABYTES;
            #pragma unroll
            for (int p = 0; p < 4; p++)
                cp16(sa + swz(lr + p * 32, ac), Ag + (size_t)(lr + p * 32) * GK2 + ka + ac * 8);
            #pragma unroll
            for (int p = 0; p < 2; p++)
                cp16(sb + swz(lr + p * 32, ac), Bg + (size_t)(lr + p * 32) * GK2 + kb + ac * 8);
            CP_COMMIT();
        }

        const uint32_t sa = sbase + (ks % W64_STAGES) * STB64;
        const uint32_t sb = sa + SM_ABYTES;
        #pragma unroll
        for (int kh = 0; kh < 2; kh++) {
            uint32_t afr[4][4], bfr[2][4];
            const int cc = kh * 2 + flc;
            #pragma unroll
            for (int mi = 0; mi < 4; mi++)
                ldsm4(afr[mi], sa + swz(wm * 64 + mi * 16 + flr, cc));
            #pragma unroll
            for (int ni = 0; ni < 2; ni++)
                ldsm4(bfr[ni], sb + swz(wn * 32 + ni * 16 + flr, cc));
            #pragma unroll
            for (int mi = 0; mi < 4; mi++)
                #pragma unroll
                for (int ni = 0; ni < 2; ni++)
                    #pragma unroll
                    for (int nn = 0; nn < 2; nn++)
                        mma16816(acc[mi][ni * 2 + nn], afr[mi],
                                 bfr[ni][nn], bfr[ni][nn + 2]);
        }
    }

    #pragma unroll
    for (int mi = 0; mi < 4; mi++) {
        const int row0 = rowBase + wm * 64 + mi * 16 + (lane >> 2);
        #pragma unroll
        for (int j = 0; j < 4; j++) {
            const int col = colBase + wn * 32 + j * 8 + (lane & 3) * 2;
            const float2 bv = *(const float2*)(bp + col);
            float2 o0, o1;
            o0.x = acc[mi][j][0] + bv.x; o0.y = acc[mi][j][1] + bv.y;
            o1.x = acc[mi][j][2] + bv.x; o1.y = acc[mi][j][3] + bv.y;
            *(float2*)(C + (size_t)row0 * D_MODEL + col) = o0;
            *(float2*)(C + (size_t)(row0 + 8) * D_MODEL + col) = o1;
        }
    }
}

// ---------------------------------------------------------------------------
// 128x64 HMMA GEMM @ 256 threads, occ 2, 3 stages (for the small G GEMM).
// ---------------------------------------------------------------------------
__global__ __launch_bounds__(256, 2) void gemm_hmma64(
    const __nv_bfloat16* __restrict__ A,
    const __nv_bfloat16* __restrict__ B, size_t bStride,
    const float* __restrict__ bias, int biasStride,
    float* __restrict__ C, int segShift)
{
    __shared__ __align__(1024) char smem[G64_STAGES * STB64];
    const int tid  = threadIdx.x;
    const int lane = tid & 31, wid = tid >> 5;
    const int wm = wid & 3, wn = wid >> 2;       // 4 x 2 warps
    const int rowBase = blockIdx.y * 128;
    const int colBase = blockIdx.x * 64;
    const int seg = rowBase >> segShift;
    const uint32_t sbase = smem_u32(smem);

    const __nv_bfloat16* Ag = A + (size_t)rowBase * GK2;
    const __nv_bfloat16* Bg = B + (size_t)seg * bStride + (size_t)colBase * GK2;
    const float* bp = bias + (size_t)seg * biasStride;

    const int lr = tid >> 2;
    const int ac = tid & 3;

    float acc[2][4][4];
    #pragma unroll
    for (int mi = 0; mi < 2; mi++)
        #pragma unroll
        for (int j = 0; j < 4; j++)
            #pragma unroll
            for (int e = 0; e < 4; e++) acc[mi][j][e] = 0.0f;

    #pragma unroll
    for (int s = 0; s < G64_STAGES - 1; s++) {
        const int ka = KOFF_A(s), kb = KOFF_B(s);
        const uint32_t sa = sbase + s * STB64;
        const uint32_t sb = sa + SM_ABYTES;
        cp16(sa + swz(lr, ac),      Ag + (size_t)lr * GK2 + ka + ac * 8);
        cp16(sa + swz(lr + 64, ac), Ag + (size_t)(lr + 64) * GK2 + ka + ac * 8);
        cp16(sb + swz(lr, ac),      Bg + (size_t)lr * GK2 + kb + ac * 8);
        CP_COMMIT();
    }

    const int flr = lane & 15;
    const int flc = lane >> 4;

    for (int ks = 0; ks < NKSTEP; ks++) {
        const int rem = NKSTEP - 1 - ks;
        if (rem >= 1) { CP_WAIT1(); } else { CP_WAIT0(); }
        __syncthreads();

        if (ks + G64_STAGES - 1 < NKSTEP) {
            const int kn = ks + G64_STAGES - 1;
            const int s  = kn % G64_STAGES;
            const int ka = KOFF_A(kn), kb = KOFF_B(kn);
            const uint32_t sa = sbase + s * STB64;
            const uint32_t sb = sa + SM_ABYTES;
            cp16(sa + swz(lr, ac),      Ag + (size_t)lr * GK2 + ka + ac * 8);
            cp16(sa + swz(lr + 64, ac), Ag + (size_t)(lr + 64) * GK2 + ka + ac * 8);
            cp16(sb + swz(lr, ac),      Bg + (size_t)lr * GK2 + kb + ac * 8);
            CP_COMMIT();
        }

        const uint32_t sa = sbase + (ks % G64_STAGES) * STB64;
        const uint32_t sb = sa + SM_ABYTES;
        #pragma unroll
        for (int kh = 0; kh < 2; kh++) {
            uint32_t afr[2][4], bfr[2][4];
            const int cc = kh * 2 + flc;
            #pragma unroll
            for (int mi = 0; mi < 2; mi++)
                ldsm4(afr[mi], sa + swz(wm * 32 + mi * 16 + flr, cc));
            #pragma unroll
            for (int ni = 0; ni < 2; ni++)
                ldsm4(bfr[ni], sb + swz(wn * 32 + ni * 16 + flr, cc));
            #pragma unroll
            for (int mi = 0; mi < 2; mi++)
                #pragma unroll
                for (int ni = 0; ni < 2; ni++)
                    #pragma unroll
                    for (int nn = 0; nn < 2; nn++)
                        mma16816(acc[mi][ni * 2 + nn], afr[mi],
                                 bfr[ni][nn], bfr[ni][nn + 2]);
        }
    }

    #pragma unroll
    for (int mi = 0; mi < 2; mi++) {
        const int row0 = rowBase + wm * 32 + mi * 16 + (lane >> 2);
        #pragma unroll
        for (int j = 0; j < 4; j++) {
            const int col = colBase + wn * 32 + j * 8 + (lane & 3) * 2;
            const float2 bv = *(const float2*)(bp + col);
            float2 o0, o1;
            o0.x = acc[mi][j][0] + bv.x; o0.y = acc[mi][j][1] + bv.y;
            o1.x = acc[mi][j][2] + bv.x; o1.y = acc[mi][j][3] + bv.y;
            *(float2*)(C + (size_t)row0 * D_MODEL + col) = o0;
            *(float2*)(C + (size_t)(row0 + 8) * D_MODEL + col) = o1;
        }
    }
}

// ---------------------------------------------------------------------------
// M = K^T V / sqrt(dk), per (b,h), chunked over t (NCHUNK=32, 64 rows/chunk).
// ---------------------------------------------------------------------------
__global__ __launch_bounds__(256) void kv_partial_kernel()
{
    const int chunk = blockIdx.x;
    const int bh    = blockIdx.y;
    const int b = bh / NHEAD, h = bh % NHEAD;
    const int tid = threadIdx.x;
    const int tx = tid & 15, ty = tid >> 4;

    __shared__ float ks[8][64];
    __shared__ float vs[8][64];

    const int rowBase = b * SEQ + chunk * CHUNK_T;
    const int colOff  = h * DK;

    const int li = tid * 2;
    const int lr = li >> 6;
    const int lc = li & 63;

    float acc[4][4];
    #pragma unroll
    for (int i = 0; i < 4; i++)
        #pragma unroll
        for (int j = 0; j < 4; j++) acc[i][j] = 0.0f;

    const float* Kp = g_KVp;
    const float* Vp = g_KVp + (size_t)NTOK * D_MODEL;

    for (int tt = 0; tt < CHUNK_T; tt += 8) {
        const size_t off = (size_t)(rowBase + tt + lr) * D_MODEL + colOff + lc;
        const float2 k2 = *(const float2*)(Kp + off);
        const float2 v2 = *(const float2*)(Vp + off);
        __syncthreads();
        ks[lr][lc] = k2.x; ks[lr][lc + 1] = k2.y;
        vs[lr][lc] = v2.x; vs[lr][lc + 1] = v2.y;
        __syncthreads();

        #pragma unroll
        for (int r = 0; r < 8; r++) {
            const float a0 = ks[r][ty * 4 + 0];
            const float a1 = ks[r][ty * 4 + 1];
            const float a2 = ks[r][ty * 4 + 2];
            const float a3 = ks[r][ty * 4 + 3];
            const float b0 = vs[r][tx * 4 + 0];
            const float b1 = vs[r][tx * 4 + 1];
            const float b2 = vs[r][tx * 4 + 2];
            const float b3 = vs[r][tx * 4 + 3];
            acc[0][0] += a0 * b0; acc[0][1] += a0 * b1; acc[0][2] += a0 * b2; acc[0][3] += a0 * b3;
            acc[1][0] += a1 * b0; acc[1][1] += a1 * b1; acc[1][2] += a1 * b2; acc[1][3] += a1 * b3;
            acc[2][0] += a2 * b0; acc[2][1] += a2 * b1; acc[2][2] += a2 * b2; acc[2][3] += a2 * b3;
            acc[3][0] += a3 * b0; acc[3][1] += a3 * b1; acc[3][2] += a3 * b2; acc[3][3] += a3 * b3;
        }
    }

    float* mp = g_Mpart + ((size_t)bh * NCHUNK + chunk) * DK * DK;
    #pragma unroll
    for (int i = 0; i < 4; i++)
        #pragma unroll
        for (int j = 0; j < 4; j++)
            mp[(ty * 4 + i) * DK + tx * 4 + j] = acc[i][j];
}

// Parallel reduce: grid (BHTOT, 16); each block reduces 256 elems over 32 chunks.
__global__ __launch_bounds__(256) void kv_reduce_kernel()
{
    const int bh = blockIdx.x;
    const int e  = blockIdx.y * 256 + threadIdx.x;
    const float* base = g_Mpart + (size_t)bh * NCHUNK * DK * DK + e;
    float s = 0.0f;
    #pragma unroll
    for (int c = 0; c < NCHUNK; c++)
        s += base[(size_t)c * DK * DK];
    g_M[(size_t)bh * DK * DK + e] = s * SCALE;
}

// ---------------------------------------------------------------------------
// T_b[i][h*64+j] = sum_l W_q[i][h*64+l] * M_b[h][l][j]
// ---------------------------------------------------------------------------
__global__ __launch_bounds__(256) void t_kernel(const float* __restrict__ w_q)
{
    const int bh = blockIdx.x;
    const int b = bh / NHEAD, h = bh % NHEAD;
    const int i0 = blockIdx.y * 64;
    const int tid = threadIdx.x;

    __shared__ float Ms[DK][DK];
    __shared__ float Ws[DK][DK];

    for (int i = tid; i < DK * DK; i += 256) {
        Ms[i >> 6][i & 63] = g_M[(size_t)bh * DK * DK + i];
        Ws[i >> 6][i & 63] = w_q[(size_t)(i0 + (i >> 6)) * D_MODEL + h * DK + (i & 63)];
    }
    __syncthreads();

    const int c  = tid & 63;
    const int rg = tid >> 6;
    for (int r = rg * 16; r < rg * 16 + 16; r++) {
        float acc = 0.0f;
        #pragma unroll 16
        for (int l = 0; l < DK; l++) acc += Ws[r][l] * Ms[l][c];
        g_T[(size_t)(b * D_MODEL + i0 + r) * D_MODEL + h * DK + c] = acc;
    }
}

// ---------------------------------------------------------------------------
// Finish: convert_w(G, both batches) + cvec in one launch.
// ---------------------------------------------------------------------------
__global__ __launch_bounds__(256) void finish_kernel(
    const float* __restrict__ b_q, const float* __restrict__ w_o,
    const float* __restrict__ b_o)
{
    __shared__ float t[32][33];
    __shared__ float bqM[D_MODEL];
    __shared__ float part[128];
    const int bx = blockIdx.x;
    const int tid = threadIdx.x;

    if (bx < 1152) {
        const int z = bx / 576, b = bx - z * 576;
        wconv_body(g_G + (size_t)z * D_MODEL * D_MODEL,
                   g_Gext + (size_t)z * D_MODEL * GK2,
                   (b % 24) * 32, (b / 24) * 32, t);
        return;
    }
    const int r = bx - 1152;           // 0..11
    const int b  = r / 6;
    const int m0 = (r % 6) * 128;

    for (int n = tid; n < D_MODEL; n += 256) {
        const int h = n >> 6, j = n & 63;
        float s = 0.0f;
        #pragma unroll 16
        for (int i = 0; i < DK; i++)
            s += b_q[h * DK + i] * g_M[(size_t)(b * NHEAD + h) * DK * DK + i * DK + j];
        bqM[n] = s;
    }
    __syncthreads();

    const int m    = m0 + (tid & 127);
    const int half = tid >> 7;
    float s = 0.0f;
    for (int n = half * 384; n < half * 384 + 384; n++)
        s += bqM[n] * w_o[(size_t)n * D_MODEL + m];
    if (half) part[tid & 127] = s;
    __syncthreads();
    if (!half)
        g_cvec[b * D_MODEL + m] = s + part[tid & 127] + b_o[m];
}

// ---------------------------------------------------------------------------
// Exact mask handling (projected through W_o). All-ones mask => pure scan.
// Vectorized int4 scan.
// ---------------------------------------------------------------------------
__global__ __launch_bounds__(256) void mask_correction_kernel(
    const int* __restrict__ mask, const float* __restrict__ q,
    const float* __restrict__ w_q, const float* __restrict__ b_q,
    const float* __restrict__ w_o, float* __restrict__ out)
{
    const int s = blockIdx.x;
    const int4* mrow = (const int4*)(mask + (size_t)s * SEQ);
    const float* Kp = g_KVp;
    const float* Vp = g_KVp + (size_t)NTOK * D_MODEL;
    for (int t4i = threadIdx.x; t4i < SEQ / 4; t4i += 256) {
        const int4 mq = mrow[t4i];
        if ((mq.x & mq.y & mq.z & mq.w) != 0) continue;
        #pragma unroll
        for (int u = 0; u < 4; u++) {
            const int mv = u == 0 ? mq.x : (u == 1 ? mq.y : (u == 2 ? mq.z : mq.w));
            if (mv != 0) continue;
            const int t = t4i * 4 + u;
            for (int b = 0; b < BATCH; b++) {
                const float* qrow = q + (size_t)(b * SEQ + s) * D_MODEL;
                const float* krow = Kp + (size_t)(b * SEQ + t) * D_MODEL;
                const float* vrow = Vp + (size_t)(b * SEQ + t) * D_MODEL;
                float* orow = out + (size_t)(b * SEQ + s) * D_MODEL;
                for (int h = 0; h < NHEAD; h++) {
                    float raw = 0.0f;
                    for (int l = 0; l < DK; l++) {
                        float qp = b_q[h * DK + l];
                        for (int i = 0; i < D_MODEL; i++)
                            qp += qrow[i] * w_q[(size_t)i * D_MODEL + h * DK + l];
                        raw += qp * krow[h * DK + l];
                    }
                    const float delta = NEGV - raw * SCALE;
                    for (int m = 0; m < D_MODEL; m++) {
                        float pv = 0.0f;
                        for (int j = 0; j < DK; j++)
                            pv += vrow[h * DK + j] * w_o[(size_t)(h * DK + j) * D_MODEL + m];
                        atomicAdd(&orow[m], delta * pv);
                    }
                }
            }
        }
    }
}

// ---------------------------------------------------------------------------
extern "C" void kernel_launch(void* const* d_in, const int* in_sizes, int n_in,
                              void* d_out, int out_size)
{
    const float* q    = (const float*)d_in[0];
    const float* k    = (const float*)d_in[1];
    const float* v    = (const float*)d_in[2];
    const int*   mask = (const int*)  d_in[3];
    const float* w_q  = (const float*)d_in[4];
    const float* b_q  = (const float*)d_in[5];
    const float* w_k  = (const float*)d_in[6];
    const float* b_k  = (const float*)d_in[7];
    const float* w_v  = (const float*)d_in[8];
    const float* b_v  = (const float*)d_in[9];
    const float* w_o  = (const float*)d_in[10];
    const float* b_o  = (const float*)d_in[11];
    float* out = (float*)d_out;

    float *KVp, *T, *G, *cvec, *zero, *biasKV;
    __nv_bfloat16 *Qext, *Aext, *Text, *Wext, *Woext, *Gext;
    cudaGetSymbolAddress((void**)&KVp,    g_KVp);
    cudaGetSymbolAddress((void**)&T,      g_T);
    cudaGetSymbolAddress((void**)&G,      g_G);
    cudaGetSymbolAddress((void**)&cvec,   g_cvec);
    cudaGetSymbolAddress((void**)&zero,   g_zero);
    cudaGetSymbolAddress((void**)&biasKV, g_biasKV);
    cudaGetSymbolAddress((void**)&Qext,   g_Qext);
    cudaGetSymbolAddress((void**)&Aext,   g_Aext);
    cudaGetSymbolAddress((void**)&Text,   g_Text);
    cudaGetSymbolAddress((void**)&Wext,   g_Wext);
    cudaGetSymbolAddress((void**)&Woext,  g_Woext);
    cudaGetSymbolAddress((void**)&Gext,   g_Gext);

    const int tTotal = 2 * D_MODEL * D_MODEL;
    const int t4Blocks = (tTotal / 4 + 255) / 256;
    const dim3 ggKV(D_MODEL / 64, 2 * NTOK / 128);         // (12, 64)
    const dim3 ggFin(D_MODEL / 64, NTOK / 128);            // (12, 32)
    const dim3 ggG(D_MODEL / 64, 2 * D_MODEL / 128);       // (12, 12)

    // 1. all independent conversions in one launch (k, v, q, wk, wv, wo)
    convert_all<<<3 * ACTB + 3 * 576, 256>>>(k, v, q, w_k, w_v, w_o);
    cudaMemcpyAsync(biasKV,           b_k, D_MODEL * sizeof(float), cudaMemcpyDeviceToDevice);
    cudaMemcpyAsync(biasKV + D_MODEL, b_v, D_MODEL * sizeof(float), cudaMemcpyDeviceToDevice);

    // 2. merged K+V projection
    gemm_w64<<<ggKV, 128>>>(Aext, Wext, (size_t)D_MODEL * GK2,
                            biasKV, D_MODEL, KVp, 12);

    // 3-4. M = K^T V / sqrt(dk)
    kv_partial_kernel<<<dim3(NCHUNK, BHTOT), 256>>>();
    kv_reduce_kernel<<<dim3(BHTOT, 16), 256>>>();

    // 5-7. T_b = W_q BD(M_b);  G_b = T_b @ W_o
    t_kernel<<<dim3(BHTOT, D_MODEL / 64), 256>>>(w_q);
    convert_act4<<<t4Blocks, 256>>>(T, Text, tTotal);
    gemm_hmma64<<<ggG, 256>>>(Text, Woext, 0, zero, 0, G, 30);

    // 8. Gext conversion + cvec (one launch)
    finish_kernel<<<1152 + 12, 256>>>(b_q, w_o, b_o);

    // 9. out[b] = q[b] @ G_b + cvec_b
    gemm_w64<<<ggFin, 128>>>(Qext, Gext, (size_t)D_MODEL * GK2,
                             cvec, D_MODEL, out, 11);

    // 10. exact mask handling (no-op for all-ones mask)
    mask_correction_kernel<<<SEQ, 256>>>(mask, q, w_q, b_q, w_o, out);
}

// round 16
// speedup vs baseline: 1.4555x; 1.1074x over previous
#include <cuda_runtime.h>
#include <cuda_bf16.h>
#include <cstdint>

// ---------------------------------------------------------------------------
// MHA without softmax, folded:
//   out[b] = q[b] @ G_b + c_b,  G_b = W_q · blockdiag(M_b) · W_o,
//   M_b = K_b^T V_b / sqrt(dk)
// GEMMs (bf16 [hi|lo] K=1536, 3-segment): merged KV (8192 rows), G (1536),
// final (4096). R16 = R15 + kv_partial atomics into g_M (no kv_reduce) +
// cvec folded into t_kernel launch.
// ---------------------------------------------------------------------------

#define D_MODEL 768
#define SEQ     2048
#define BATCH   2
#define NTOK    (BATCH*SEQ)          // 4096
#define NHEAD   12
#define DK      64
#define BHTOT   (BATCH*NHEAD)        // 24
#define NCHUNK  32
#define CHUNK_T (SEQ/NCHUNK)         // 64
#define SCALE   0.125f
#define NEGV    (-1000000000.0f)

#define GK2     1536                 // split K: [hi | lo]
#define BK      32
#define SEGSTEP (D_MODEL/BK)         // 24
#define NKSTEP  (3*SEGSTEP)          // 72
#define SM_ABYTES  8192              // 128 rows * 64B
#define SM_B64     4096              // 64 rows * 64B
#define STB64  (SM_ABYTES + SM_B64)
#define W64_STAGES 4
#define G64_STAGES 3

// Scratch (allocation-free)
__device__ float g_KVp[2*NTOK*D_MODEL];       // rows 0..4095 = Kp, 4096.. = Vp
__device__ float g_M[BHTOT*DK*DK];
__device__ float g_T[2*D_MODEL*D_MODEL];
__device__ float g_G[2*D_MODEL*D_MODEL];
__device__ float g_cvec[2*D_MODEL];
__device__ float g_zero[D_MODEL];
__device__ float g_biasKV[2*D_MODEL];
__device__ __nv_bfloat16 g_Qext[(size_t)NTOK*GK2];
__device__ __nv_bfloat16 g_Aext[(size_t)2*NTOK*GK2];
__device__ __nv_bfloat16 g_Text[(size_t)2*D_MODEL*GK2];
__device__ __nv_bfloat16 g_Wext[(size_t)2*D_MODEL*GK2];
__device__ __nv_bfloat16 g_Woext[(size_t)D_MODEL*GK2];
__device__ __nv_bfloat16 g_Gext[(size_t)2*D_MODEL*GK2];

// ---------------------------------------------------------------------------
// PTX helpers (generic sm_80+ ISA only)
// ---------------------------------------------------------------------------
__device__ __forceinline__ uint32_t smem_u32(const void* p) {
    uint32_t a;
    asm("{ .reg .u64 t; cvta.to.shared.u64 t, %1; cvt.u32.u64 %0, t; }" : "=r"(a) : "l"(p));
    return a;
}
__device__ __forceinline__ void cp16(uint32_t saddr, const void* g) {
    asm volatile("cp.async.cg.shared.global [%0], [%1], 16;" :: "r"(saddr), "l"(g));
}
#define CP_COMMIT() asm volatile("cp.async.commit_group;" ::: "memory")
#define CP_WAIT0()  asm volatile("cp.async.wait_group 0;" ::: "memory")
#define CP_WAIT1()  asm volatile("cp.async.wait_group 1;" ::: "memory")
#define CP_WAIT2()  asm volatile("cp.async.wait_group 2;" ::: "memory")

__device__ __forceinline__ void ldsm4(uint32_t* r, uint32_t addr) {
    asm volatile("ldmatrix.sync.aligned.m8n8.x4.shared.b16 {%0,%1,%2,%3}, [%4];"
                 : "=r"(r[0]), "=r"(r[1]), "=r"(r[2]), "=r"(r[3]) : "r"(addr));
}
__device__ __forceinline__ void mma16816(float* c, const uint32_t* a,
                                         uint32_t b0, uint32_t b1) {
    asm volatile(
        "mma.sync.aligned.m16n8k16.row.col.f32.bf16.bf16.f32 "
        "{%0,%1,%2,%3}, {%4,%5,%6,%7}, {%8,%9}, {%0,%1,%2,%3};"
        : "+f"(c[0]), "+f"(c[1]), "+f"(c[2]), "+f"(c[3])
        : "r"(a[0]), "r"(a[1]), "r"(a[2]), "r"(a[3]), "r"(b0), "r"(b1));
}
__device__ __forceinline__ uint32_t swz(int r, int c) {
    return (uint32_t)(r * 64 + ((c ^ ((r >> 1) & 3)) << 4));
}

#define KOFF_A(ks) (((ks) >= 2*SEGSTEP ? 768 : 0) + ((ks) % SEGSTEP) * BK)
#define KOFF_B(ks) ((((ks) >= SEGSTEP && (ks) < 2*SEGSTEP) ? 768 : 0) + ((ks) % SEGSTEP) * BK)

// ---------------------------------------------------------------------------
// Conversion bodies (shared by mega-fused kernels)
// ---------------------------------------------------------------------------
__device__ __forceinline__ void act4_body(
    const float* __restrict__ in, __nv_bfloat16* __restrict__ out, int blk)
{
    const int idx = blk * 256 + threadIdx.x;
    const int e = idx * 4;
    const int r = e / D_MODEL, c = e - r * D_MODEL;
    float4 a = *(const float4*)(in + e);
    __nv_bfloat16 h0 = __float2bfloat16_rn(a.x), h1 = __float2bfloat16_rn(a.y);
    __nv_bfloat16 h2 = __float2bfloat16_rn(a.z), h3 = __float2bfloat16_rn(a.w);
    __nv_bfloat16 l0 = __float2bfloat16_rn(a.x - __bfloat162float(h0));
    __nv_bfloat16 l1 = __float2bfloat16_rn(a.y - __bfloat162float(h1));
    __nv_bfloat16 l2 = __float2bfloat16_rn(a.z - __bfloat162float(h2));
    __nv_bfloat16 l3 = __float2bfloat16_rn(a.w - __bfloat162float(h3));
    uint2 hv, lv;
    hv.x = (uint32_t)__bfloat16_as_ushort(h0) | ((uint32_t)__bfloat16_as_ushort(h1) << 16);
    hv.y = (uint32_t)__bfloat16_as_ushort(h2) | ((uint32_t)__bfloat16_as_ushort(h3) << 16);
    lv.x = (uint32_t)__bfloat16_as_ushort(l0) | ((uint32_t)__bfloat16_as_ushort(l1) << 16);
    lv.y = (uint32_t)__bfloat16_as_ushort(l2) | ((uint32_t)__bfloat16_as_ushort(l3) << 16);
    size_t ro = (size_t)r * GK2;
    *(uint2*)(out + ro + c)       = hv;
    *(uint2*)(out + ro + 768 + c) = lv;
}

__device__ __forceinline__ void wconv_body(
    const float* __restrict__ W, __nv_bfloat16* __restrict__ out,
    int k0, int n0, float (*t)[33])
{
    const int tx = threadIdx.x & 31, ty = threadIdx.x >> 5;
    #pragma unroll
    for (int i = 0; i < 32; i += 8)
        t[ty + i][tx] = W[(size_t)(k0 + ty + i) * D_MODEL + n0 + tx];
    __syncthreads();
    #pragma unroll
    for (int i = 0; i < 32; i += 8) {
        const int n = n0 + ty + i, k = k0 + tx;
        const float w = t[tx][ty + i];
        __nv_bfloat16 hi = __float2bfloat16_rn(w);
        __nv_bfloat16 lo = __float2bfloat16_rn(w - __bfloat162float(hi));
        size_t ro = (size_t)n * GK2;
        out[ro + k]       = hi;
        out[ro + 768 + k] = lo;
    }
}

// All six independent conversions + g_M zeroing in ONE launch.
#define ACTB 3072
#define WCONVB (3 * 576)
#define MZEROB 96
__global__ __launch_bounds__(256) void convert_all(
    const float* __restrict__ k, const float* __restrict__ v,
    const float* __restrict__ q,
    const float* __restrict__ w_k, const float* __restrict__ w_v,
    const float* __restrict__ w_o)
{
    __shared__ float t[32][33];
    const int bx = blockIdx.x;
    if (bx < 3 * ACTB) {
        const int tsel = bx / ACTB, blk = bx - tsel * ACTB;
        const float* in = tsel == 0 ? k : (tsel == 1 ? v : q);
        __nv_bfloat16* out = tsel == 0 ? g_Aext
                           : (tsel == 1 ? g_Aext + (size_t)NTOK * GK2 : g_Qext);
        act4_body(in, out, blk);
    } else if (bx < 3 * ACTB + WCONVB) {
        const int wi = bx - 3 * ACTB;
        const int widx = wi / 576, b = wi - widx * 576;
        const float* W = widx == 0 ? w_k : (widx == 1 ? w_v : w_o);
        __nv_bfloat16* out = widx == 0 ? g_Wext
                           : (widx == 1 ? g_Wext + (size_t)D_MODEL * GK2 : g_Woext);
        wconv_body(W, out, (b % 24) * 32, (b / 24) * 32, t);
    } else {
        // zero g_M (24*4096 floats = 96 blocks * 256 threads * 4 floats)
        const int zi = (bx - 3 * ACTB - WCONVB) * 256 + threadIdx.x;
        *(float4*)(g_M + (size_t)zi * 4) = make_float4(0.f, 0.f, 0.f, 0.f);
    }
}

// convert_act4 kept for the T matrix (mid-chain dependency)
__global__ __launch_bounds__(256) void convert_act4(
    const float* __restrict__ in, __nv_bfloat16* __restrict__ out, int total)
{
    int idx = blockIdx.x * 256 + threadIdx.x;
    if (idx * 4 >= total) return;
    act4_body(in, out, blockIdx.x);
}

// ---------------------------------------------------------------------------
// Big-GEMM: 128x64 CTA, 128 threads (4 warps 2x2), 64x32 warp tiles, 4 stages.
// ---------------------------------------------------------------------------
__global__ __launch_bounds__(128) void gemm_w64(
    const __nv_bfloat16* __restrict__ A,
    const __nv_bfloat16* __restrict__ B, size_t bStride,
    const float* __restrict__ bias, int biasStride,
    float* __restrict__ C, int segShift)
{
    __shared__ __align__(1024) char smem[W64_STAGES * STB64];
    const int tid  = threadIdx.x;
    const int lane = tid & 31, wid = tid >> 5;
    const int wm = wid & 1, wn = wid >> 1;          // 2 x 2 warps
    const int rowBase = blockIdx.y * 128;
    const int colBase = blockIdx.x * 64;
    const int seg = rowBase >> segShift;
    const uint32_t sbase = smem_u32(smem);

    const __nv_bfloat16* Ag = A + (size_t)rowBase * GK2;
    const __nv_bfloat16* Bg = B + (size_t)seg * bStride + (size_t)colBase * GK2;
    const float* bp = bias + (size_t)seg * biasStride;

    const int lr = tid >> 2;      // 0..31
    const int ac = tid & 3;

    float acc[4][4][4];
    #pragma unroll
    for (int mi = 0; mi < 4; mi++)
        #pragma unroll
        for (int j = 0; j < 4; j++)
            #pragma unroll
            for (int e = 0; e < 4; e++) acc[mi][j][e] = 0.0f;

    #pragma unroll
    for (int s = 0; s < W64_STAGES - 1; s++) {
        const int ka = KOFF_A(s), kb = KOFF_B(s);
        const uint32_t sa = sbase + s * STB64;
        const uint32_t sb = sa + SM_ABYTES;
        #pragma unroll
        for (int p = 0; p < 4; p++)
            cp16(sa + swz(lr + p * 32, ac), Ag + (size_t)(lr + p * 32) * GK2 + ka + ac * 8);
        #pragma unroll
        for (int p = 0; p < 2; p++)
            cp16(sb + swz(lr + p * 32, ac), Bg + (size_t)(lr + p * 32) * GK2 + kb + ac * 8);
        CP_COMMIT();
    }

    const int flr = lane & 15;
    const int flc = lane >> 4;

    for (int ks = 0; ks < NKSTEP; ks++) {
        const int rem = NKSTEP - 1 - ks;
        if (rem >= 2) { CP_WAIT2(); } else if (rem == 1) { CP_WAIT1(); } else { CP_WAIT0(); }
        __syncthreads();

        if (ks + W64_STAGES - 1 < NKSTEP) {
            const int kn = ks + W64_STAGES - 1;
            const int s  = kn % W64_STAGES;
            const int ka = KOFF_A(kn), kb = KOFF_B(kn);
            const uint32_t sa = sbase + s * STB64;
            const uint32_t sb = sa + SM_ABYTES;
            #pragma unroll
            for (int p = 0; p < 4; p++)
                cp16(sa + swz(lr + p * 32, ac), Ag + (size_t)(lr + p * 32) * GK2 + ka + ac * 8);
            #pragma unroll
            for (int p = 0; p < 2; p++)
                cp16(sb + swz(lr + p * 32, ac), Bg + (size_t)(lr + p * 32) * GK2 + kb + ac * 8);
            CP_COMMIT();
        }

        const uint32_t sa = sbase + (ks % W64_STAGES) * STB64;
        const uint32_t sb = sa + SM_ABYTES;
        #pragma unroll
        for (int kh = 0; kh < 2; kh++) {
            uint32_t afr[4][4], bfr[2][4];
            const int cc = kh * 2 + flc;
            #pragma unroll
            for (int mi = 0; mi < 4; mi++)
                ldsm4(afr[mi], sa + swz(wm * 64 + mi * 16 + flr, cc));
            #pragma unroll
            for (int ni = 0; ni < 2; ni++)
                ldsm4(bfr[ni], sb + swz(wn * 32 + ni * 16 + flr, cc));
            #pragma unroll
            for (int mi = 0; mi < 4; mi++)
                #pragma unroll
                for (int ni = 0; ni < 2; ni++)
                    #pragma unroll
                    for (int nn = 0; nn < 2; nn++)
                        mma16816(acc[mi][ni * 2 + nn], afr[mi],
                                 bfr[ni][nn], bfr[ni][nn + 2]);
        }
    }

    #pragma unroll
    for (int mi = 0; mi < 4; mi++) {
        const int row0 = rowBase + wm * 64 + mi * 16 + (lane >> 2);
        #pragma unroll
        for (int j = 0; j < 4; j++) {
            const int col = colBase + wn * 32 + j * 8 + (lane & 3) * 2;
            const float2 bv = *(const float2*)(bp + col);
            float2 o0, o1;
            o0.x = acc[mi][j][0] + bv.x; o0.y = acc[mi][j][1] + bv.y;
            o1.x = acc[mi][j][2] + bv.x; o1.y = acc[mi][j][3] + bv.y;
            *(float2*)(C + (size_t)row0 * D_MODEL + col) = o0;
            *(float2*)(C + (size_t)(row0 + 8) * D_MODEL + col) = o1;
        }
    }
}

// ---------------------------------------------------------------------------
// 128x64 HMMA GEMM @ 256 threads, occ 2, 3 stages (for the small G GEMM).
// ---------------------------------------------------------------------------
__global__ __launch_bounds__(256, 2) void gemm_hmma64(
    const __nv_bfloat16* __restrict__ A,
    const __nv_bfloat16* __restrict__ B, size_t bStride,
    const float* __restrict__ bias, int biasStride,
    float* __restrict__ C, int segShift)
{
    __shared__ __align__(1024) char smem[G64_STAGES * STB64];
    const int tid  = threadIdx.x;
    const int lane = tid & 31, wid = tid >> 5;
    const int wm = wid & 3, wn = wid >> 2;       // 4 x 2 warps
    const int rowBase = blockIdx.y * 128;
    const int colBase = blockIdx.x * 64;
    const int seg = rowBase >> segShift;
    const uint32_t sbase = smem_u32(smem);

    const __nv_bfloat16* Ag = A + (size_t)rowBase * GK2;
    const __nv_bfloat16* Bg = B + (size_t)seg * bStride + (size_t)colBase * GK2;
    const float* bp = bias + (size_t)seg * biasStride;

    const int lr = tid >> 2;
    const int ac = tid & 3;

    float acc[2][4][4];
    #pragma unroll
    for (int mi = 0; mi < 2; mi++)
        #pragma unroll
        for (int j = 0; j < 4; j++)
            #pragma unroll
            for (int e = 0; e < 4; e++) acc[mi][j][e] = 0.0f;

    #pragma unroll
    for (int s = 0; s < G64_STAGES - 1; s++) {
        const int ka = KOFF_A(s), kb = KOFF_B(s);
        const uint32_t sa = sbase + s * STB64;
        const uint32_t sb = sa + SM_ABYTES;
        cp16(sa + swz(lr, ac),      Ag + (size_t)lr * GK2 + ka + ac * 8);
        cp16(sa + swz(lr + 64, ac), Ag + (size_t)(lr + 64) * GK2 + ka + ac * 8);
        cp16(sb + swz(lr, ac),      Bg + (size_t)lr * GK2 + kb + ac * 8);
        CP_COMMIT();
    }

    const int flr = lane & 15;
    const int flc = lane >> 4;

    for (int ks = 0; ks < NKSTEP; ks++) {
        const int rem = NKSTEP - 1 - ks;
        if (rem >= 1) { CP_WAIT1(); } else { CP_WAIT0(); }
        __syncthreads();

        if (ks + G64_STAGES - 1 < NKSTEP) {
            const int kn = ks + G64_STAGES - 1;
            const int s  = kn % G64_STAGES;
            const int ka = KOFF_A(kn), kb = KOFF_B(kn);
            const uint32_t sa = sbase + s * STB64;
            const uint32_t sb = sa + SM_ABYTES;
            cp16(sa + swz(lr, ac),      Ag + (size_t)lr * GK2 + ka + ac * 8);
            cp16(sa + swz(lr + 64, ac), Ag + (size_t)(lr + 64) * GK2 + ka + ac * 8);
            cp16(sb + swz(lr, ac),      Bg + (size_t)lr * GK2 + kb + ac * 8);
            CP_COMMIT();
        }

        const uint32_t sa = sbase + (ks % G64_STAGES) * STB64;
        const uint32_t sb = sa + SM_ABYTES;
        #pragma unroll
        for (int kh = 0; kh < 2; kh++) {
            uint32_t afr[2][4], bfr[2][4];
            const int cc = kh * 2 + flc;
            #pragma unroll
            for (int mi = 0; mi < 2; mi++)
                ldsm4(afr[mi], sa + swz(wm * 32 + mi * 16 + flr, cc));
            #pragma unroll
            for (int ni = 0; ni < 2; ni++)
                ldsm4(bfr[ni], sb + swz(wn * 32 + ni * 16 + flr, cc));
            #pragma unroll
            for (int mi = 0; mi < 2; mi++)
                #pragma unroll
                for (int ni = 0; ni < 2; ni++)
                    #pragma unroll
                    for (int nn = 0; nn < 2; nn++)
                        mma16816(acc[mi][ni * 2 + nn], afr[mi],
                                 bfr[ni][nn], bfr[ni][nn + 2]);
        }
    }

    #pragma unroll
    for (int mi = 0; mi < 2; mi++) {
        const int row0 = rowBase + wm * 32 + mi * 16 + (lane >> 2);
        #pragma unroll
        for (int j = 0; j < 4; j++) {
            const int col = colBase + wn * 32 + j * 8 + (lane & 3) * 2;
            const float2 bv = *(const float2*)(bp + col);
            float2 o0, o1;
            o0.x = acc[mi][j][0] + bv.x; o0.y = acc[mi][j][1] + bv.y;
            o1.x = acc[mi][j][2] + bv.x; o1.y = acc[mi][j][3] + bv.y;
            *(float2*)(C + (size_t)row0 * D_MODEL + col) = o0;
            *(float2*)(C + (size_t)(row0 + 8) * D_MODEL + col) = o1;
        }
    }
}

// ---------------------------------------------------------------------------
// M = K^T V / sqrt(dk): partials accumulated directly into g_M via atomics.
// g_M zeroed by convert_all (launch 1). Grid (NCHUNK, BHTOT).
// ---------------------------------------------------------------------------
__global__ __launch_bounds__(256) void kv_partial_kernel()
{
    const int chunk = blockIdx.x;
    const int bh    = blockIdx.y;
    const int b = bh / NHEAD, h = bh % NHEAD;
    const int tid = threadIdx.x;
    const int tx = tid & 15, ty = tid >> 4;

    __shared__ float ks[8][64];
    __shared__ float vs[8][64];

    const int rowBase = b * SEQ + chunk * CHUNK_T;
    const int colOff  = h * DK;

    const int li = tid * 2;
    const int lr = li >> 6;
    const int lc = li & 63;

    float acc[4][4];
    #pragma unroll
    for (int i = 0; i < 4; i++)
        #pragma unroll
        for (int j = 0; j < 4; j++) acc[i][j] = 0.0f;

    const float* Kp = g_KVp;
    const float* Vp = g_KVp + (size_t)NTOK * D_MODEL;

    for (int tt = 0; tt < CHUNK_T; tt += 8) {
        const size_t off = (size_t)(rowBase + tt + lr) * D_MODEL + colOff + lc;
        const float2 k2 = *(const float2*)(Kp + off);
        const float2 v2 = *(const float2*)(Vp + off);
        __syncthreads();
        ks[lr][lc] = k2.x; ks[lr][lc + 1] = k2.y;
        vs[lr][lc] = v2.x; vs[lr][lc + 1] = v2.y;
        __syncthreads();

        #pragma unroll
        for (int r = 0; r < 8; r++) {
            const float a0 = ks[r][ty * 4 + 0];
            const float a1 = ks[r][ty * 4 + 1];
            const float a2 = ks[r][ty * 4 + 2];
            const float a3 = ks[r][ty * 4 + 3];
            const float b0 = vs[r][tx * 4 + 0];
            const float b1 = vs[r][tx * 4 + 1];
            const float b2 = vs[r][tx * 4 + 2];
            const float b3 = vs[r][tx * 4 + 3];
            acc[0][0] += a0 * b0; acc[0][1] += a0 * b1; acc[0][2] += a0 * b2; acc[0][3] += a0 * b3;
            acc[1][0] += a1 * b0; acc[1][1] += a1 * b1; acc[1][2] += a1 * b2; acc[1][3] += a1 * b3;
            acc[2][0] += a2 * b0; acc[2][1] += a2 * b1; acc[2][2] += a2 * b2; acc[2][3] += a2 * b3;
            acc[3][0] += a3 * b0; acc[3][1] += a3 * b1; acc[3][2] += a3 * b2; acc[3][3] += a3 * b3;
        }
    }

    float* mp = g_M + (size_t)bh * DK * DK;
    #pragma unroll
    for (int i = 0; i < 4; i++)
        #pragma unroll
        for (int j = 0; j < 4; j++)
            atomicAdd(&mp[(ty * 4 + i) * DK + tx * 4 + j], acc[i][j] * SCALE);
}

// ---------------------------------------------------------------------------
// T_b[i][h*64+j] = sum_l W_q[i][h*64+l] * M_b[h][l][j].
// blockIdx.y == 12 row carries the cvec computation (12 active blocks).
// ---------------------------------------------------------------------------
__global__ __launch_bounds__(256) void t_kernel(
    const float* __restrict__ w_q, const float* __restrict__ b_q,
    const float* __restrict__ w_o, const float* __restrict__ b_o)
{
    const int tid = threadIdx.x;

    if (blockIdx.y == 12) {
        if (blockIdx.x >= 12) return;
        __shared__ float bqM[D_MODEL];
        __shared__ float part[128];
        const int b  = blockIdx.x / 6;
        const int m0 = (blockIdx.x % 6) * 128;

        for (int n = tid; n < D_MODEL; n += 256) {
            const int h = n >> 6, j = n & 63;
            float s = 0.0f;
            #pragma unroll 16
            for (int i = 0; i < DK; i++)
                s += b_q[h * DK + i] * g_M[(size_t)(b * NHEAD + h) * DK * DK + i * DK + j];
            bqM[n] = s;
        }
        __syncthreads();

        const int m    = m0 + (tid & 127);
        const int half = tid >> 7;
        float s = 0.0f;
        for (int n = half * 384; n < half * 384 + 384; n++)
            s += bqM[n] * w_o[(size_t)n * D_MODEL + m];
        if (half) part[tid & 127] = s;
        __syncthreads();
        if (!half)
            g_cvec[b * D_MODEL + m] = s + part[tid & 127] + b_o[m];
        return;
    }

    const int bh = blockIdx.x;
    const int b = bh / NHEAD, h = bh % NHEAD;
    const int i0 = blockIdx.y * 64;

    __shared__ float Ms[DK][DK];
    __shared__ float Ws[DK][DK];

    for (int i = tid; i < DK * DK; i += 256) {
        Ms[i >> 6][i & 63] = g_M[(size_t)bh * DK * DK + i];
        Ws[i >> 6][i & 63] = w_q[(size_t)(i0 + (i >> 6)) * D_MODEL + h * DK + (i & 63)];
    }
    __syncthreads();

    const int c  = tid & 63;
    const int rg = tid >> 6;
    for (int r = rg * 16; r < rg * 16 + 16; r++) {
        float acc = 0.0f;
        #pragma unroll 16
        for (int l = 0; l < DK; l++) acc += Ws[r][l] * Ms[l][c];
        g_T[(size_t)(b * D_MODEL + i0 + r) * D_MODEL + h * DK + c] = acc;
    }
}

// ---------------------------------------------------------------------------
// Finish: convert_w(G, both batches) -> Gext.
// ---------------------------------------------------------------------------
__global__ __launch_bounds__(256) void finish_kernel()
{
    __shared__ float t[32][33];
    const int bx = blockIdx.x;
    const int z = bx / 576, b = bx - z * 576;
    wconv_body(g_G + (size_t)z * D_MODEL * D_MODEL,
               g_Gext + (size_t)z * D_MODEL * GK2,
               (b % 24) * 32, (b / 24) * 32, t);
}

// ---------------------------------------------------------------------------
// Exact mask handling (projected through W_o). All-ones mask => pure scan.
// Vectorized int4 scan.
// ---------------------------------------------------------------------------
__global__ __launch_bounds__(256) void mask_correction_kernel(
    const int* __restrict__ mask, const float* __restrict__ q,
    const float* __restrict__ w_q, const float* __restrict__ b_q,
    const float* __restrict__ w_o, float* __restrict__ out)
{
    const int s = blockIdx.x;
    const int4* mrow = (const int4*)(mask + (size_t)s * SEQ);
    const float* Kp = g_KVp;
    const float* Vp = g_KVp + (size_t)NTOK * D_MODEL;
    for (int t4i = threadIdx.x; t4i < SEQ / 4; t4i += 256) {
        const int4 mq = mrow[t4i];
        if ((mq.x & mq.y & mq.z & mq.w) != 0) continue;
        #pragma unroll
        for (int u = 0; u < 4; u++) {
            const int mv = u == 0 ? mq.x : (u == 1 ? mq.y : (u == 2 ? mq.z : mq.w));
            if (mv != 0) continue;
            const int t = t4i * 4 + u;
            for (int b = 0; b < BATCH; b++) {
                const float* qrow = q + (size_t)(b * SEQ + s) * D_MODEL;
                const float* krow = Kp + (size_t)(b * SEQ + t) * D_MODEL;
                const float* vrow = Vp + (size_t)(b * SEQ + t) * D_MODEL;
                float* orow = out + (size_t)(b * SEQ + s) * D_MODEL;
                for (int h = 0; h < NHEAD; h++) {
                    float raw = 0.0f;
                    for (int l = 0; l < DK; l++) {
                        float qp = b_q[h * DK + l];
                        for (int i = 0; i < D_MODEL; i++)
                            qp += qrow[i] * w_q[(size_t)i * D_MODEL + h * DK + l];
                        raw += qp * krow[h * DK + l];
                    }
                    const float delta = NEGV - raw * SCALE;
                    for (int m = 0; m < D_MODEL; m++) {
                        float pv = 0.0f;
                        for (int j = 0; j < DK; j++)
                            pv += vrow[h * DK + j] * w_o[(size_t)(h * DK + j) * D_MODEL + m];
                        atomicAdd(&orow[m], delta * pv);
                    }
                }
            }
        }
    }
}

// ---------------------------------------------------------------------------
extern "C" void kernel_launch(void* const* d_in, const int* in_sizes, int n_in,
                              void* d_out, int out_size)
{
    const float* q    = (const float*)d_in[0];
    const float* k    = (const float*)d_in[1];
    const float* v    = (const float*)d_in[2];
    const int*   mask = (const int*)  d_in[3];
    const float* w_q  = (const float*)d_in[4];
    const float* b_q  = (const float*)d_in[5];
    const float* w_k  = (const float*)d_in[6];
    const float* b_k  = (const float*)d_in[7];
    const float* w_v  = (const float*)d_in[8];
    const float* b_v  = (const float*)d_in[9];
    const float* w_o  = (const float*)d_in[10];
    const float* b_o  = (const float*)d_in[11];
    float* out = (float*)d_out;

    float *KVp, *T, *G, *cvec, *zero, *biasKV;
    __nv_bfloat16 *Qext, *Aext, *Text, *Wext, *Woext, *Gext;
    cudaGetSymbolAddress((void**)&KVp,    g_KVp);
    cudaGetSymbolAddress((void**)&T,      g_T);
    cudaGetSymbolAddress((void**)&G,      g_G);
    cudaGetSymbolAddress((void**)&cvec,   g_cvec);
    cudaGetSymbolAddress((void**)&zero,   g_zero);
    cudaGetSymbolAddress((void**)&biasKV, g_biasKV);
    cudaGetSymbolAddress((void**)&Qext,   g_Qext);
    cudaGetSymbolAddress((void**)&Aext,   g_Aext);
    cudaGetSymbolAddress((void**)&Text,   g_Text);
    cudaGetSymbolAddress((void**)&Wext,   g_Wext);
    cudaGetSymbolAddress((void**)&Woext,  g_Woext);
    cudaGetSymbolAddress((void**)&Gext,   g_Gext);

    const int tTotal = 2 * D_MODEL * D_MODEL;
    const int t4Blocks = (tTotal / 4 + 255) / 256;
    const dim3 ggKV(D_MODEL / 64, 2 * NTOK / 128);         // (12, 64)
    const dim3 ggFin(D_MODEL / 64, NTOK / 128);            // (12, 32)
    const dim3 ggG(D_MODEL / 64, 2 * D_MODEL / 128);       // (12, 12)

    // 1. conversions (k, v, q, wk, wv, wo) + g_M zeroing in one launch
    convert_all<<<3 * ACTB + WCONVB + MZEROB, 256>>>(k, v, q, w_k, w_v, w_o);
    cudaMemcpyAsync(biasKV,           b_k, D_MODEL * sizeof(float), cudaMemcpyDeviceToDevice);
    cudaMemcpyAsync(biasKV + D_MODEL, b_v, D_MODEL * sizeof(float), cudaMemcpyDeviceToDevice);

    // 2. merged K+V projection
    gemm_w64<<<ggKV, 128>>>(Aext, Wext, (size_t)D_MODEL * GK2,
                            biasKV, D_MODEL, KVp, 12);

    // 3. M = K^T V / sqrt(dk)  (atomic accumulate into zeroed g_M)
    kv_partial_kernel<<<dim3(NCHUNK, BHTOT), 256>>>();

    // 4. T_b = W_q BD(M_b) + cvec (one launch)
    t_kernel<<<dim3(BHTOT, D_MODEL / 64 + 1), 256>>>(w_q, b_q, w_o, b_o);

    // 5. Text conversion; 6. G_b = T_b @ W_o
    convert_act4<<<t4Blocks, 256>>>(T, Text, tTotal);
    gemm_hmma64<<<ggG, 256>>>(Text, Woext, 0, zero, 0, G, 30);

    // 7. Gext conversion
    finish_kernel<<<1152, 256>>>();

    // 8. out[b] = q[b] @ G_b + cvec_b
    gemm_w64<<<ggFin, 128>>>(Qext, Gext, (size_t)D_MODEL * GK2,
                             cvec, D_MODEL, out, 11);

    // 9. exact mask handling (no-op for all-ones mask)
    mask_correction_kernel<<<SEQ, 256>>>(mask, q, w_q, b_q, w_o, out);
}

// round 17
// speedup vs baseline: 1.4772x; 1.0149x over previous
#include <cuda_runtime.h>
#include <cuda_bf16.h>
#include <cstdint>

// ---------------------------------------------------------------------------
// MHA without softmax, folded:
//   out[b] = q[b] @ G_b + c_b,  G_b = W_q · blockdiag(M_b) · W_o,
//   M_b = K_b^T V_b / sqrt(dk)
// GEMMs (bf16 [hi|lo] K=1536, 3-segment): merged KV (8192 rows), G (1536),
// final (4096). R17 = R16 + register-blocked t_kernel (4x4 tiles, float4 LDS).
// ---------------------------------------------------------------------------

#define D_MODEL 768
#define SEQ     2048
#define BATCH   2
#define NTOK    (BATCH*SEQ)          // 4096
#define NHEAD   12
#define DK      64
#define BHTOT   (BATCH*NHEAD)        // 24
#define NCHUNK  32
#define CHUNK_T (SEQ/NCHUNK)         // 64
#define SCALE   0.125f
#define NEGV    (-1000000000.0f)

#define GK2     1536                 // split K: [hi | lo]
#define BK      32
#define SEGSTEP (D_MODEL/BK)         // 24
#define NKSTEP  (3*SEGSTEP)          // 72
#define SM_ABYTES  8192              // 128 rows * 64B
#define SM_B64     4096              // 64 rows * 64B
#define STB64  (SM_ABYTES + SM_B64)
#define W64_STAGES 4
#define G64_STAGES 3

// Scratch (allocation-free)
__device__ float g_KVp[2*NTOK*D_MODEL];       // rows 0..4095 = Kp, 4096.. = Vp
__device__ float g_M[BHTOT*DK*DK];
__device__ float g_T[2*D_MODEL*D_MODEL];
__device__ float g_G[2*D_MODEL*D_MODEL];
__device__ float g_cvec[2*D_MODEL];
__device__ float g_zero[D_MODEL];
__device__ float g_biasKV[2*D_MODEL];
__device__ __nv_bfloat16 g_Qext[(size_t)NTOK*GK2];
__device__ __nv_bfloat16 g_Aext[(size_t)2*NTOK*GK2];
__device__ __nv_bfloat16 g_Text[(size_t)2*D_MODEL*GK2];
__device__ __nv_bfloat16 g_Wext[(size_t)2*D_MODEL*GK2];
__device__ __nv_bfloat16 g_Woext[(size_t)D_MODEL*GK2];
__device__ __nv_bfloat16 g_Gext[(size_t)2*D_MODEL*GK2];

// ---------------------------------------------------------------------------
// PTX helpers (generic sm_80+ ISA only)
// ---------------------------------------------------------------------------
__device__ __forceinline__ uint32_t smem_u32(const void* p) {
    uint32_t a;
    asm("{ .reg .u64 t; cvta.to.shared.u64 t, %1; cvt.u32.u64 %0, t; }" : "=r"(a) : "l"(p));
    return a;
}
__device__ __forceinline__ void cp16(uint32_t saddr, const void* g) {
    asm volatile("cp.async.cg.shared.global [%0], [%1], 16;" :: "r"(saddr), "l"(g));
}
#define CP_COMMIT() asm volatile("cp.async.commit_group;" ::: "memory")
#define CP_WAIT0()  asm volatile("cp.async.wait_group 0;" ::: "memory")
#define CP_WAIT1()  asm volatile("cp.async.wait_group 1;" ::: "memory")
#define CP_WAIT2()  asm volatile("cp.async.wait_group 2;" ::: "memory")

__device__ __forceinline__ void ldsm4(uint32_t* r, uint32_t addr) {
    asm volatile("ldmatrix.sync.aligned.m8n8.x4.shared.b16 {%0,%1,%2,%3}, [%4];"
                 : "=r"(r[0]), "=r"(r[1]), "=r"(r[2]), "=r"(r[3]) : "r"(addr));
}
__device__ __forceinline__ void mma16816(float* c, const uint32_t* a,
                                         uint32_t b0, uint32_t b1) {
    asm volatile(
        "mma.sync.aligned.m16n8k16.row.col.f32.bf16.bf16.f32 "
        "{%0,%1,%2,%3}, {%4,%5,%6,%7}, {%8,%9}, {%0,%1,%2,%3};"
        : "+f"(c[0]), "+f"(c[1]), "+f"(c[2]), "+f"(c[3])
        : "r"(a[0]), "r"(a[1]), "r"(a[2]), "r"(a[3]), "r"(b0), "r"(b1));
}
__device__ __forceinline__ uint32_t swz(int r, int c) {
    return (uint32_t)(r * 64 + ((c ^ ((r >> 1) & 3)) << 4));
}

#define KOFF_A(ks) (((ks) >= 2*SEGSTEP ? 768 : 0) + ((ks) % SEGSTEP) * BK)
#define KOFF_B(ks) ((((ks) >= SEGSTEP && (ks) < 2*SEGSTEP) ? 768 : 0) + ((ks) % SEGSTEP) * BK)

// ---------------------------------------------------------------------------
// Conversion bodies (shared by mega-fused kernels)
// ---------------------------------------------------------------------------
__device__ __forceinline__ void act4_body(
    const float* __restrict__ in, __nv_bfloat16* __restrict__ out, int blk)
{
    const int idx = blk * 256 + threadIdx.x;
    const int e = idx * 4;
    const int r = e / D_MODEL, c = e - r * D_MODEL;
    float4 a = *(const float4*)(in + e);
    __nv_bfloat16 h0 = __float2bfloat16_rn(a.x), h1 = __float2bfloat16_rn(a.y);
    __nv_bfloat16 h2 = __float2bfloat16_rn(a.z), h3 = __float2bfloat16_rn(a.w);
    __nv_bfloat16 l0 = __float2bfloat16_rn(a.x - __bfloat162float(h0));
    __nv_bfloat16 l1 = __float2bfloat16_rn(a.y - __bfloat162float(h1));
    __nv_bfloat16 l2 = __float2bfloat16_rn(a.z - __bfloat162float(h2));
    __nv_bfloat16 l3 = __float2bfloat16_rn(a.w - __bfloat162float(h3));
    uint2 hv, lv;
    hv.x = (uint32_t)__bfloat16_as_ushort(h0) | ((uint32_t)__bfloat16_as_ushort(h1) << 16);
    hv.y = (uint32_t)__bfloat16_as_ushort(h2) | ((uint32_t)__bfloat16_as_ushort(h3) << 16);
    lv.x = (uint32_t)__bfloat16_as_ushort(l0) | ((uint32_t)__bfloat16_as_ushort(l1) << 16);
    lv.y = (uint32_t)__bfloat16_as_ushort(l2) | ((uint32_t)__bfloat16_as_ushort(l3) << 16);
    size_t ro = (size_t)r * GK2;
    *(uint2*)(out + ro + c)       = hv;
    *(uint2*)(out + ro + 768 + c) = lv;
}

__device__ __forceinline__ void wconv_body(
    const float* __restrict__ W, __nv_bfloat16* __restrict__ out,
    int k0, int n0, float (*t)[33])
{
    const int tx = threadIdx.x & 31, ty = threadIdx.x >> 5;
    #pragma unroll
    for (int i = 0; i < 32; i += 8)
        t[ty + i][tx] = W[(size_t)(k0 + ty + i) * D_MODEL + n0 + tx];
    __syncthreads();
    #pragma unroll
    for (int i = 0; i < 32; i += 8) {
        const int n = n0 + ty + i, k = k0 + tx;
        const float w = t[tx][ty + i];
        __nv_bfloat16 hi = __float2bfloat16_rn(w);
        __nv_bfloat16 lo = __float2bfloat16_rn(w - __bfloat162float(hi));
        size_t ro = (size_t)n * GK2;
        out[ro + k]       = hi;
        out[ro + 768 + k] = lo;
    }
}

// All six independent conversions + g_M zeroing in ONE launch.
#define ACTB 3072
#define WCONVB (3 * 576)
#define MZEROB 96
__global__ __launch_bounds__(256) void convert_all(
    const float* __restrict__ k, const float* __restrict__ v,
    const float* __restrict__ q,
    const float* __restrict__ w_k, const float* __restrict__ w_v,
    const float* __restrict__ w_o)
{
    __shared__ float t[32][33];
    const int bx = blockIdx.x;
    if (bx < 3 * ACTB) {
        const int tsel = bx / ACTB, blk = bx - tsel * ACTB;
        const float* in = tsel == 0 ? k : (tsel == 1 ? v : q);
        __nv_bfloat16* out = tsel == 0 ? g_Aext
                           : (tsel == 1 ? g_Aext + (size_t)NTOK * GK2 : g_Qext);
        act4_body(in, out, blk);
    } else if (bx < 3 * ACTB + WCONVB) {
        const int wi = bx - 3 * ACTB;
        const int widx = wi / 576, b = wi - widx * 576;
        const float* W = widx == 0 ? w_k : (widx == 1 ? w_v : w_o);
        __nv_bfloat16* out = widx == 0 ? g_Wext
                           : (widx == 1 ? g_Wext + (size_t)D_MODEL * GK2 : g_Woext);
        wconv_body(W, out, (b % 24) * 32, (b / 24) * 32, t);
    } else {
        const int zi = (bx - 3 * ACTB - WCONVB) * 256 + threadIdx.x;
        *(float4*)(g_M + (size_t)zi * 4) = make_float4(0.f, 0.f, 0.f, 0.f);
    }
}

// convert_act4 kept for the T matrix (mid-chain dependency)
__global__ __launch_bounds__(256) void convert_act4(
    const float* __restrict__ in, __nv_bfloat16* __restrict__ out, int total)
{
    int idx = blockIdx.x * 256 + threadIdx.x;
    if (idx * 4 >= total) return;
    act4_body(in, out, blockIdx.x);
}

// ---------------------------------------------------------------------------
// Big-GEMM: 128x64 CTA, 128 threads (4 warps 2x2), 64x32 warp tiles, 4 stages.
// ---------------------------------------------------------------------------
__global__ __launch_bounds__(128) void gemm_w64(
    const __nv_bfloat16* __restrict__ A,
    const __nv_bfloat16* __restrict__ B, size_t bStride,
    const float* __restrict__ bias, int biasStride,
    float* __restrict__ C, int segShift)
{
    __shared__ __align__(1024) char smem[W64_STAGES * STB64];
    const int tid  = threadIdx.x;
    const int lane = tid & 31, wid = tid >> 5;
    const int wm = wid & 1, wn = wid >> 1;          // 2 x 2 warps
    const int rowBase = blockIdx.y * 128;
    const int colBase = blockIdx.x * 64;
    const int seg = rowBase >> segShift;
    const uint32_t sbase = smem_u32(smem);

    const __nv_bfloat16* Ag = A + (size_t)rowBase * GK2;
    const __nv_bfloat16* Bg = B + (size_t)seg * bStride + (size_t)colBase * GK2;
    const float* bp = bias + (size_t)seg * biasStride;

    const int lr = tid >> 2;      // 0..31
    const int ac = tid & 3;

    float acc[4][4][4];
    #pragma unroll
    for (int mi = 0; mi < 4; mi++)
        #pragma unroll
        for (int j = 0; j < 4; j++)
            #pragma unroll
            for (int e = 0; e < 4; e++) acc[mi][j][e] = 0.0f;

    #pragma unroll
    for (int s = 0; s < W64_STAGES - 1; s++) {
        const int ka = KOFF_A(s), kb = KOFF_B(s);
        const uint32_t sa = sbase + s * STB64;
        const uint32_t sb = sa + SM_ABYTES;
        #pragma unroll
        for (int p = 0; p < 4; p++)
            cp16(sa + swz(lr + p * 32, ac), Ag + (size_t)(lr + p * 32) * GK2 + ka + ac * 8);
        #pragma unroll
        for (int p = 0; p < 2; p++)
            cp16(sb + swz(lr + p * 32, ac), Bg + (size_t)(lr + p * 32) * GK2 + kb + ac * 8);
        CP_COMMIT();
    }

    const int flr = lane & 15;
    const int flc = lane >> 4;

    for (int ks = 0; ks < NKSTEP; ks++) {
        const int rem = NKSTEP - 1 - ks;
        if (rem >= 2) { CP_WAIT2(); } else if (rem == 1) { CP_WAIT1(); } else { CP_WAIT0(); }
        __syncthreads();

        if (ks + W64_STAGES - 1 < NKSTEP) {
            const int kn = ks + W64_STAGES - 1;
            const int s  = kn % W64_STAGES;
            const int ka = KOFF_A(kn), kb = KOFF_B(kn);
            const uint32_t sa = sbase + s * STB64;
            const uint32_t sb = sa + SM_ABYTES;
            #pragma unroll
            for (int p = 0; p < 4; p++)
                cp16(sa + swz(lr + p * 32, ac), Ag + (size_t)(lr + p * 32) * GK2 + ka + ac * 8);
            #pragma unroll
            for (int p = 0; p < 2; p++)
                cp16(sb + swz(lr + p * 32, ac), Bg + (size_t)(lr + p * 32) * GK2 + kb + ac * 8);
            CP_COMMIT();
        }

        const uint32_t sa = sbase + (ks % W64_STAGES) * STB64;
        const uint32_t sb = sa + SM_ABYTES;
        #pragma unroll
        for (int kh = 0; kh < 2; kh++) {
            uint32_t afr[4][4], bfr[2][4];
            const int cc = kh * 2 + flc;
            #pragma unroll
            for (int mi = 0; mi < 4; mi++)
                ldsm4(afr[mi], sa + swz(wm * 64 + mi * 16 + flr, cc));
            #pragma unroll
            for (int ni = 0; ni < 2; ni++)
                ldsm4(bfr[ni], sb + swz(wn * 32 + ni * 16 + flr, cc));
            #pragma unroll
            for (int mi = 0; mi < 4; mi++)
                #pragma unroll
                for (int ni = 0; ni < 2; ni++)
                    #pragma unroll
                    for (int nn = 0; nn < 2; nn++)
                        mma16816(acc[mi][ni * 2 + nn], afr[mi],
                                 bfr[ni][nn], bfr[ni][nn + 2]);
        }
    }

    #pragma unroll
    for (int mi = 0; mi < 4; mi++) {
        const int row0 = rowBase + wm * 64 + mi * 16 + (lane >> 2);
        #pragma unroll
        for (int j = 0; j < 4; j++) {
            const int col = colBase + wn * 32 + j * 8 + (lane & 3) * 2;
            const float2 bv = *(const float2*)(bp + col);
            float2 o0, o1;
            o0.x = acc[mi][j][0] + bv.x; o0.y = acc[mi][j][1] + bv.y;
            o1.x = acc[mi][j][2] + bv.x; o1.y = acc[mi][j][3] + bv.y;
            *(float2*)(C + (size_t)row0 * D_MODEL + col) = o0;
            *(float2*)(C + (size_t)(row0 + 8) * D_MODEL + col) = o1;
        }
    }
}

// ---------------------------------------------------------------------------
// 128x64 HMMA GEMM @ 256 threads, occ 2, 3 stages (for the small G GEMM).
// ---------------------------------------------------------------------------
__global__ __launch_bounds__(256, 2) void gemm_hmma64(
    const __nv_bfloat16* __restrict__ A,
    const __nv_bfloat16* __restrict__ B, size_t bStride,
    const float* __restrict__ bias, int biasStride,
    float* __restrict__ C, int segShift)
{
    __shared__ __align__(1024) char smem[G64_STAGES * STB64];
    const int tid  = threadIdx.x;
    const int lane = tid & 31, wid = tid >> 5;
    const int wm = wid & 3, wn = wid >> 2;       // 4 x 2 warps
    const int rowBase = blockIdx.y * 128;
    const int colBase = blockIdx.x * 64;
    const int seg = rowBase >> segShift;
    const uint32_t sbase = smem_u32(smem);

    const __nv_bfloat16* Ag = A + (size_t)rowBase * GK2;
    const __nv_bfloat16* Bg = B + (size_t)seg * bStride + (size_t)colBase * GK2;
    const float* bp = bias + (size_t)seg * biasStride;

    const int lr = tid >> 2;
    const int ac = tid & 3;

    float acc[2][4][4];
    #pragma unroll
    for (int mi = 0; mi < 2; mi++)
        #pragma unroll
        for (int j = 0; j < 4; j++)
            #pragma unroll
            for (int e = 0; e < 4; e++) acc[mi][j][e] = 0.0f;

    #pragma unroll
    for (int s = 0; s < G64_STAGES - 1; s++) {
        const int ka = KOFF_A(s), kb = KOFF_B(s);
        const uint32_t sa = sbase + s * STB64;
        const uint32_t sb = sa + SM_ABYTES;
        cp16(sa + swz(lr, ac),      Ag + (size_t)lr * GK2 + ka + ac * 8);
        cp16(sa + swz(lr + 64, ac), Ag + (size_t)(lr + 64) * GK2 + ka + ac * 8);
        cp16(sb + swz(lr, ac),      Bg + (size_t)lr * GK2 + kb + ac * 8);
        CP_COMMIT();
    }

    const int flr = lane & 15;
    const int flc = lane >> 4;

    for (int ks = 0; ks < NKSTEP; ks++) {
        const int rem = NKSTEP - 1 - ks;
        if (rem >= 1) { CP_WAIT1(); } else { CP_WAIT0(); }
        __syncthreads();

        if (ks + G64_STAGES - 1 < NKSTEP) {
            const int kn = ks + G64_STAGES - 1;
            const int s  = kn % G64_STAGES;
            const int ka = KOFF_A(kn), kb = KOFF_B(kn);
            const uint32_t sa = sbase + s * STB64;
            const uint32_t sb = sa + SM_ABYTES;
            cp16(sa + swz(lr, ac),      Ag + (size_t)lr * GK2 + ka + ac * 8);
            cp16(sa + swz(lr + 64, ac), Ag + (size_t)(lr + 64) * GK2 + ka + ac * 8);
            cp16(sb + swz(lr, ac),      Bg + (size_t)lr * GK2 + kb + ac * 8);
            CP_COMMIT();
        }

        const uint32_t sa = sbase + (ks % G64_STAGES) * STB64;
        const uint32_t sb = sa + SM_ABYTES;
        #pragma unroll
        for (int kh = 0; kh < 2; kh++) {
            uint32_t afr[2][4], bfr[2][4];
            const int cc = kh * 2 + flc;
            #pragma unroll
            for (int mi = 0; mi < 2; mi++)
                ldsm4(afr[mi], sa + swz(wm * 32 + mi * 16 + flr, cc));
            #pragma unroll
            for (int ni = 0; ni < 2; ni++)
                ldsm4(bfr[ni], sb + swz(wn * 32 + ni * 16 + flr, cc));
            #pragma unroll
            for (int mi = 0; mi < 2; mi++)
                #pragma unroll
                for (int ni = 0; ni < 2; ni++)
                    #pragma unroll
                    for (int nn = 0; nn < 2; nn++)
                        mma16816(acc[mi][ni * 2 + nn], afr[mi],
                                 bfr[ni][nn], bfr[ni][nn + 2]);
        }
    }

    #pragma unroll
    for (int mi = 0; mi < 2; mi++) {
        const int row0 = rowBase + wm * 32 + mi * 16 + (lane >> 2);
        #pragma unroll
        for (int j = 0; j < 4; j++) {
            const int col = colBase + wn * 32 + j * 8 + (lane & 3) * 2;
            const float2 bv = *(const float2*)(bp + col);
            float2 o0, o1;
            o0.x = acc[mi][j][0] + bv.x; o0.y = acc[mi][j][1] + bv.y;
            o1.x = acc[mi][j][2] + bv.x; o1.y = acc[mi][j][3] + bv.y;
            *(float2*)(C + (size_t)row0 * D_MODEL + col) = o0;
            *(float2*)(C + (size_t)(row0 + 8) * D_MODEL + col) = o1;
        }
    }
}

// ---------------------------------------------------------------------------
// M = K^T V / sqrt(dk): partials accumulated directly into g_M via atomics.
// g_M zeroed by convert_all (launch 1). Grid (NCHUNK, BHTOT).
// ---------------------------------------------------------------------------
__global__ __launch_bounds__(256) void kv_partial_kernel()
{
    const int chunk = blockIdx.x;
    const int bh    = blockIdx.y;
    const int b = bh / NHEAD, h = bh % NHEAD;
    const int tid = threadIdx.x;
    const int tx = tid & 15, ty = tid >> 4;

    __shared__ float ks[8][64];
    __shared__ float vs[8][64];

    const int rowBase = b * SEQ + chunk * CHUNK_T;
    const int colOff  = h * DK;

    const int li = tid * 2;
    const int lr = li >> 6;
    const int lc = li & 63;

    float acc[4][4];
    #pragma unroll
    for (int i = 0; i < 4; i++)
        #pragma unroll
        for (int j = 0; j < 4; j++) acc[i][j] = 0.0f;

    const float* Kp = g_KVp;
    const float* Vp = g_KVp + (size_t)NTOK * D_MODEL;

    for (int tt = 0; tt < CHUNK_T; tt += 8) {
        const size_t off = (size_t)(rowBase + tt + lr) * D_MODEL + colOff + lc;
        const float2 k2 = *(const float2*)(Kp + off);
        const float2 v2 = *(const float2*)(Vp + off);
        __syncthreads();
        ks[lr][lc] = k2.x; ks[lr][lc + 1] = k2.y;
        vs[lr][lc] = v2.x; vs[lr][lc + 1] = v2.y;
        __syncthreads();

        #pragma unroll
        for (int r = 0; r < 8; r++) {
            const float a0 = ks[r][ty * 4 + 0];
            const float a1 = ks[r][ty * 4 + 1];
            const float a2 = ks[r][ty * 4 + 2];
            const float a3 = ks[r][ty * 4 + 3];
            const float b0 = vs[r][tx * 4 + 0];
            const float b1 = vs[r][tx * 4 + 1];
            const float b2 = vs[r][tx * 4 + 2];
            const float b3 = vs[r][tx * 4 + 3];
            acc[0][0] += a0 * b0; acc[0][1] += a0 * b1; acc[0][2] += a0 * b2; acc[0][3] += a0 * b3;
            acc[1][0] += a1 * b0; acc[1][1] += a1 * b1; acc[1][2] += a1 * b2; acc[1][3] += a1 * b3;
            acc[2][0] += a2 * b0; acc[2][1] += a2 * b1; acc[2][2] += a2 * b2; acc[2][3] += a2 * b3;
            acc[3][0] += a3 * b0; acc[3][1] += a3 * b1; acc[3][2] += a3 * b2; acc[3][3] += a3 * b3;
        }
    }

    float* mp = g_M + (size_t)bh * DK * DK;
    #pragma unroll
    for (int i = 0; i < 4; i++)
        #pragma unroll
        for (int j = 0; j < 4; j++)
            atomicAdd(&mp[(ty * 4 + i) * DK + tx * 4 + j], acc[i][j] * SCALE);
}

// ---------------------------------------------------------------------------
// T_b[i][h*64+j] = sum_l W_q[i][h*64+l] * M_b[h][l][j].
// Register-blocked: each thread computes a 4x4 tile (float4 Ms loads).
// blockIdx.y == 12 row carries the cvec computation (12 active blocks).
// ---------------------------------------------------------------------------
__global__ __launch_bounds__(256) void t_kernel(
    const float* __restrict__ w_q, const float* __restrict__ b_q,
    const float* __restrict__ w_o, const float* __restrict__ b_o)
{
    const int tid = threadIdx.x;

    if (blockIdx.y == 12) {
        if (blockIdx.x >= 12) return;
        __shared__ float bqM[D_MODEL];
        __shared__ float part[128];
        const int b  = blockIdx.x / 6;
        const int m0 = (blockIdx.x % 6) * 128;

        for (int n = tid; n < D_MODEL; n += 256) {
            const int h = n >> 6, j = n & 63;
            float s = 0.0f;
            #pragma unroll 16
            for (int i = 0; i < DK; i++)
                s += b_q[h * DK + i] * g_M[(size_t)(b * NHEAD + h) * DK * DK + i * DK + j];
            bqM[n] = s;
        }
        __syncthreads();

        const int m    = m0 + (tid & 127);
        const int half = tid >> 7;
        float s = 0.0f;
        for (int n = half * 384; n < half * 384 + 384; n++)
            s += bqM[n] * w_o[(size_t)n * D_MODEL + m];
        if (half) part[tid & 127] = s;
        __syncthreads();
        if (!half)
            g_cvec[b * D_MODEL + m] = s + part[tid & 127] + b_o[m];
        return;
    }

    const int bh = blockIdx.x;
    const int b = bh / NHEAD, h = bh % NHEAD;
    const int i0 = blockIdx.y * 64;

    __shared__ float Ms[DK][DK];
    __shared__ float Ws[DK][DK];

    for (int i = tid; i < DK * DK; i += 256) {
        Ms[i >> 6][i & 63] = g_M[(size_t)bh * DK * DK + i];
        Ws[i >> 6][i & 63] = w_q[(size_t)(i0 + (i >> 6)) * D_MODEL + h * DK + (i & 63)];
    }
    __syncthreads();

    // 4x4 register tile per thread: rows tr*4.., cols tc*4..
    const int tr = tid >> 4;      // 0..15
    const int tc = tid & 15;      // 0..15
    float acc[4][4];
    #pragma unroll
    for (int i = 0; i < 4; i++)
        #pragma unroll
        for (int j = 0; j < 4; j++) acc[i][j] = 0.0f;

    #pragma unroll 4
    for (int l = 0; l < DK; l++) {
        const float4 mv = *(const float4*)&Ms[l][tc * 4];
        #pragma unroll
        for (int i = 0; i < 4; i++) {
            const float w = Ws[tr * 4 + i][l];
            acc[i][0] += w * mv.x;
            acc[i][1] += w * mv.y;
            acc[i][2] += w * mv.z;
            acc[i][3] += w * mv.w;
        }
    }

    #pragma unroll
    for (int i = 0; i < 4; i++) {
        float* tp = g_T + (size_t)(b * D_MODEL + i0 + tr * 4 + i) * D_MODEL
                        + h * DK + tc * 4;
        *(float4*)tp = make_float4(acc[i][0], acc[i][1], acc[i][2], acc[i][3]);
    }
}

// ---------------------------------------------------------------------------
// Finish: convert_w(G, both batches) -> Gext.
// ---------------------------------------------------------------------------
__global__ __launch_bounds__(256) void finish_kernel()
{
    __shared__ float t[32][33];
    const int bx = blockIdx.x;
    const int z = bx / 576, b = bx - z * 576;
    wconv_body(g_G + (size_t)z * D_MODEL * D_MODEL,
               g_Gext + (size_t)z * D_MODEL * GK2,
               (b % 24) * 32, (b / 24) * 32, t);
}

// ---------------------------------------------------------------------------
// Exact mask handling (projected through W_o). All-ones mask => pure scan.
// Vectorized int4 scan.
// ---------------------------------------------------------------------------
__global__ __launch_bounds__(256) void mask_correction_kernel(
    const int* __restrict__ mask, const float* __restrict__ q,
    const float* __restrict__ w_q, const float* __restrict__ b_q,
    const float* __restrict__ w_o, float* __restrict__ out)
{
    const int s = blockIdx.x;
    const int4* mrow = (const int4*)(mask + (size_t)s * SEQ);
    const float* Kp = g_KVp;
    const float* Vp = g_KVp + (size_t)NTOK * D_MODEL;
    for (int t4i = threadIdx.x; t4i < SEQ / 4; t4i += 256) {
        const int4 mq = mrow[t4i];
        if ((mq.x & mq.y & mq.z & mq.w) != 0) continue;
        #pragma unroll
        for (int u = 0; u < 4; u++) {
            const int mv = u == 0 ? mq.x : (u == 1 ? mq.y : (u == 2 ? mq.z : mq.w));
            if (mv != 0) continue;
            const int t = t4i * 4 + u;
            for (int b = 0; b < BATCH; b++) {
                const float* qrow = q + (size_t)(b * SEQ + s) * D_MODEL;
                const float* krow = Kp + (size_t)(b * SEQ + t) * D_MODEL;
                const float* vrow = Vp + (size_t)(b * SEQ + t) * D_MODEL;
                float* orow = out + (size_t)(b * SEQ + s) * D_MODEL;
                for (int h = 0; h < NHEAD; h++) {
                    float raw = 0.0f;
                    for (int l = 0; l < DK; l++) {
                        float qp = b_q[h * DK + l];
                        for (int i = 0; i < D_MODEL; i++)
                            qp += qrow[i] * w_q[(size_t)i * D_MODEL + h * DK + l];
                        raw += qp * krow[h * DK + l];
                    }
                    const float delta = NEGV - raw * SCALE;
                    for (int m = 0; m < D_MODEL; m++) {
                        float pv = 0.0f;
                        for (int j = 0; j < DK; j++)
                            pv += vrow[h * DK + j] * w_o[(size_t)(h * DK + j) * D_MODEL + m];
                        atomicAdd(&orow[m], delta * pv);
                    }
                }
            }
        }
    }
}

// ---------------------------------------------------------------------------
extern "C" void kernel_launch(void* const* d_in, const int* in_sizes, int n_in,
                              void* d_out, int out_size)
{
    const float* q    = (const float*)d_in[0];
    const float* k    = (const float*)d_in[1];
    const float* v    = (const float*)d_in[2];
    const int*   mask = (const int*)  d_in[3];
    const float* w_q  = (const float*)d_in[4];
    const float* b_q  = (const float*)d_in[5];
    const float* w_k  = (const float*)d_in[6];
    const float* b_k  = (const float*)d_in[7];
    const float* w_v  = (const float*)d_in[8];
    const float* b_v  = (const float*)d_in[9];
    const float* w_o  = (const float*)d_in[10];
    const float* b_o  = (const float*)d_in[11];
    float* out = (float*)d_out;

    float *KVp, *T, *G, *cvec, *zero, *biasKV;
    __nv_bfloat16 *Qext, *Aext, *Text, *Wext, *Woext, *Gext;
    cudaGetSymbolAddress((void**)&KVp,    g_KVp);
    cudaGetSymbolAddress((void**)&T,      g_T);
    cudaGetSymbolAddress((void**)&G,      g_G);
    cudaGetSymbolAddress((void**)&cvec,   g_cvec);
    cudaGetSymbolAddress((void**)&zero,   g_zero);
    cudaGetSymbolAddress((void**)&biasKV, g_biasKV);
    cudaGetSymbolAddress((void**)&Qext,   g_Qext);
    cudaGetSymbolAddress((void**)&Aext,   g_Aext);
    cudaGetSymbolAddress((void**)&Text,   g_Text);
    cudaGetSymbolAddress((void**)&Wext,   g_Wext);
    cudaGetSymbolAddress((void**)&Woext,  g_Woext);
    cudaGetSymbolAddress((void**)&Gext,   g_Gext);

    const int tTotal = 2 * D_MODEL * D_MODEL;
    const int t4Blocks = (tTotal / 4 + 255) / 256;
    const dim3 ggKV(D_MODEL / 64, 2 * NTOK / 128);         // (12, 64)
    const dim3 ggFin(D_MODEL / 64, NTOK / 128);            // (12, 32)
    const dim3 ggG(D_MODEL / 64, 2 * D_MODEL / 128);       // (12, 12)

    // 1. conversions (k, v, q, wk, wv, wo) + g_M zeroing in one launch
    convert_all<<<3 * ACTB + WCONVB + MZEROB, 256>>>(k, v, q, w_k, w_v, w_o);
    cudaMemcpyAsync(biasKV,           b_k, D_MODEL * sizeof(float), cudaMemcpyDeviceToDevice);
    cudaMemcpyAsync(biasKV + D_MODEL, b_v, D_MODEL * sizeof(float), cudaMemcpyDeviceToDevice);

    // 2. merged K+V projection
    gemm_w64<<<ggKV, 128>>>(Aext, Wext, (size_t)D_MODEL * GK2,
                            biasKV, D_MODEL, KVp, 12);

    // 3. M = K^T V / sqrt(dk)  (atomic accumulate into zeroed g_M)
    kv_partial_kernel<<<dim3(NCHUNK, BHTOT), 256>>>();

    // 4. T_b = W_q BD(M_b) + cvec (one launch)
    t_kernel<<<dim3(BHTOT, D_MODEL / 64 + 1), 256>>>(w_q, b_q, w_o, b_o);

    // 5. Text conversion; 6. G_b = T_b @ W_o
    convert_act4<<<t4Blocks, 256>>>(T, Text, tTotal);
    gemm_hmma64<<<ggG, 256>>>(Text, Woext, 0, zero, 0, G, 30);

    // 7. Gext conversion
    finish_kernel<<<1152, 256>>>();

    // 8. out[b] = q[b] @ G_b + cvec_b
    gemm_w64<<<ggFin, 128>>>(Qext, Gext, (size_t)D_MODEL * GK2,
                             cvec, D_MODEL, out, 11);

    // 9. exact mask handling (no-op for all-ones mask)
    mask_correction_kernel<<<SEQ, 256>>>(mask, q, w_q, b_q, w_o, out);
}